// round 3
// baseline (speedup 1.0000x reference)
#include <cuda_runtime.h>

#define BB   32
#define NN   16384
#define CKD  16
#define MAXM 8192

// ---------------- device scratch (static, no allocations) ----------------
__device__ __align__(256) float g_x0 [BB*MAXM*CKD];
__device__ __align__(256) float g_x1 [BB*MAXM*CKD];
__device__ __align__(256) float g_d  [BB*MAXM*CKD];     // reused as deep-kernel output
__device__ __align__(256) float g_Ud [BB*(NN-1)*CKD];
__device__ __align__(256) float g_Us [BB*(NN-1)*CKD];
__device__ __align__(256) float g_part[2ull*BB*64*64*CKD*2];
__device__ __align__(256) float g_spec[BB*2*128*CKD];   // [b][arr][k=2f+c][j], Im negated, wf folded
__device__ __align__(256) float g_tabc[MAXM*64];        // [t][f] cos
__device__ __align__(256) float g_tabs[MAXM*64];        // [t][f] sin
__device__ __align__(256) float g_tabT[64*MAXM*2];      // [f][t](cos,sin) interleaved
__device__ __align__(256) float g_wT  [6*64*16*16];     // [arr][f][i][o]

// ---------------- twiddle tables ----------------
__global__ void tab_row_kernel() {
    int idx = blockIdx.x * blockDim.x + threadIdx.x;   // t*64 + f
    int t = idx >> 6, f = idx & 63;
    float ph = (float)(f * t) * (2.0f / 8192.0f);
    float s, c; sincospif(ph, &s, &c);
    g_tabc[idx] = c;
    g_tabs[idx] = s;
}
__global__ void tab_T_kernel() {
    int idx = blockIdx.x * blockDim.x + threadIdx.x;   // f*8192 + t
    int f = idx >> 13, t = idx & 8191;
    float ph = (float)(f * t) * (2.0f / 8192.0f);
    float s, c; sincospif(ph, &s, &c);
    g_tabT[2*idx + 0] = c;
    g_tabT[2*idx + 1] = s;
}

// ---------------- weight transpose: [i][o][f] -> [arr][f][i][o] ----------------
__global__ void wprep_kernel(const float* __restrict__ a0, const float* __restrict__ a1,
                             const float* __restrict__ a2, const float* __restrict__ a3,
                             const float* __restrict__ a4, const float* __restrict__ a5) {
    int idx = blockIdx.x * blockDim.x + threadIdx.x;
    if (idx >= 6*16384) return;
    int arr = idx >> 14;
    int r   = idx & 16383;
    int f = r >> 8, i = (r >> 4) & 15, o = r & 15;
    const float* src = (arr == 0) ? a0 : (arr == 1) ? a1 : (arr == 2) ? a2 :
                       (arr == 3) ? a3 : (arr == 4) ? a4 : a5;
    g_wT[idx] = src[(i * 16 + o) * 64 + f];
}

// =================================================================
// dfwd: fused decompose + forward truncated DFT (split-K partials)
// block: 256 threads = 8 b, grid (4, nchunk). clen = m/nchunk = 128.
// thread tile: 8 i x 4 f, both d and x arrays.
// =================================================================
__global__ void __launch_bounds__(256, 1) dfwd_kernel(
        const float* __restrict__ xin, float* __restrict__ xnext,
        const float* __restrict__ ecd, const float* __restrict__ ecs,
        int m, int stride, int nchunk) {
    extern __shared__ float sm[];
    float* s_in = sm;                 // 8*64*16 = 8192
    float* s_d  = s_in + 8192;        // 8*32*16 = 4096
    float* s_x  = s_d + 4096;         // 4096
    float* s_tc = s_x + 4096;         // 32*64 = 2048
    float* s_ts = s_tc + 2048;        // 2048
    __shared__ float fl[64];
    int tid = threadIdx.x;
    int b0 = blockIdx.x * 8;
    int ch = blockIdx.y;
    int clen = m / nchunk;
    int T0base = ch * clen;
    if (tid < 32) fl[tid] = ecd[tid];
    else if (tid < 64) fl[tid] = ecs[tid - 32];

    int lane = tid & 31, bloc = tid >> 5;
    int i0 = (lane & 1) * 8;
    int f0 = (lane >> 1) * 4;
    float aDr[8][4] = {}, aDi[8][4] = {}, aXr[8][4] = {}, aXi[8][4] = {};

    for (int tb = 0; tb < clen; tb += 32) {
        int T0 = T0base + tb;
        // ---- load input pairs + table tile ----
        {
            const float4* gx = (const float4*)xin;
            float4* si = (float4*)s_in;
            for (int id = tid; id < 2048; id += 256) {
                int bl = id >> 8;
                int r  = id & 255;
                int t  = r >> 2, q = r & 3;
                si[id] = gx[(((size_t)(b0 + bl) * (2 * m)) + (2 * T0 + t)) * 4 + q];
            }
            float4* tc4 = (float4*)s_tc;
            float4* ts4 = (float4*)s_ts;
            for (int id = tid; id < 512; id += 256) {
                int t = id >> 4, q = id & 15;
                size_t g = ((size_t)(T0 + t) * stride) * 16 + q;
                tc4[id] = ((const float4*)g_tabc)[g];
                ts4[id] = ((const float4*)g_tabs)[g];
            }
        }
        __syncthreads();
        // ---- decompose tile: 8b x 32t x 4c; also emit x_next to gmem ----
        for (int id = tid; id < 1024; id += 256) {
            int c = id & 3, t = (id >> 2) & 31, bl = id >> 7;
            float xa[8];
#pragma unroll
            for (int p = 0; p < 4; p++) {
                xa[p]     = s_in[(bl * 64 + 2 * t) * 16 + c * 4 + p];
                xa[p + 4] = s_in[(bl * 64 + 2 * t + 1) * 16 + c * 4 + p];
            }
            float dv[4] = {0, 0, 0, 0}, sv[4] = {0, 0, 0, 0};
#pragma unroll
            for (int p = 0; p < 8; p++) {
                float xv = xa[p];
#pragma unroll
                for (int j = 0; j < 4; j++) {
                    dv[j] += xv * fl[p * 4 + j];
                    sv[j] += xv * fl[32 + p * 4 + j];
                }
            }
            float4 d4 = make_float4(dv[0], dv[1], dv[2], dv[3]);
            float4 s4 = make_float4(sv[0], sv[1], sv[2], sv[3]);
            *(float4*)&s_d[(bl * 32 + t) * 16 + c * 4] = d4;
            *(float4*)&s_x[(bl * 32 + t) * 16 + c * 4] = s4;
            *(float4*)&xnext[(((size_t)(b0 + bl) * m) + T0 + t) * 16 + c * 4] = s4;
        }
        __syncthreads();
        // ---- DFT accumulation ----
#pragma unroll 2
        for (int tt = 0; tt < 32; tt++) {
            const float* bd = &s_d[(bloc * 32 + tt) * 16];
            const float* bx = &s_x[(bloc * 32 + tt) * 16];
            float4 d0 = *(const float4*)&bd[i0];
            float4 d1 = *(const float4*)&bd[i0 + 4];
            float4 x0 = *(const float4*)&bx[i0];
            float4 x1 = *(const float4*)&bx[i0 + 4];
            float4 cv = *(const float4*)&s_tc[tt * 64 + f0];
            float4 sv = *(const float4*)&s_ts[tt * 64 + f0];
            float dd[8] = {d0.x, d0.y, d0.z, d0.w, d1.x, d1.y, d1.z, d1.w};
            float xx[8] = {x0.x, x0.y, x0.z, x0.w, x1.x, x1.y, x1.z, x1.w};
            float cf[4] = {cv.x, cv.y, cv.z, cv.w};
            float sf[4] = {sv.x, sv.y, sv.z, sv.w};
#pragma unroll
            for (int ii = 0; ii < 8; ii++)
#pragma unroll
                for (int ff = 0; ff < 4; ff++) {
                    aDr[ii][ff] += dd[ii] * cf[ff];
                    aDi[ii][ff] -= dd[ii] * sf[ff];
                    aXr[ii][ff] += xx[ii] * cf[ff];
                    aXi[ii][ff] -= xx[ii] * sf[ff];
                }
        }
        __syncthreads();
    }
    // ---- write partials ----
    float2* P = (float2*)g_part;
    int b = b0 + bloc;
    size_t baseD = (((size_t)0 * BB + b) * nchunk + ch) * 64;
    size_t baseX = (((size_t)1 * BB + b) * nchunk + ch) * 64;
#pragma unroll
    for (int ff = 0; ff < 4; ff++)
#pragma unroll
        for (int ii = 0; ii < 8; ii++) {
            P[(baseD + f0 + ff) * 16 + i0 + ii] = make_float2(aDr[ii][ff], aDi[ii][ff]);
            P[(baseX + f0 + ff) * 16 + i0 + ii] = make_float2(aXr[ii][ff], aXi[ii][ff]);
        }
}

// ---------------- reduce partials + mixing + irfft weighting (Im negated) ----------------
__global__ void mix_kernel(int m, int nchunk) {
    int f = blockIdx.x;
    int b = blockIdx.y;
    int tid = threadIdx.x;          // 32 threads
    __shared__ float Dre[16], Dim[16], Xre[16], Xim[16];
    int arr = tid >> 4, i = tid & 15;
    const float2* P = (const float2*)g_part;
    float sre = 0.f, sim = 0.f;
    size_t base = (((size_t)arr * BB + b) * nchunk) * 64 + f;
    for (int ch = 0; ch < nchunk; ch++) {
        float2 p = P[(base + (size_t)ch * 64) * 16 + i];
        sre += p.x; sim += p.y;
    }
    if (arr == 0) { Dre[i] = sre; Dim[i] = sim; }
    else          { Xre[i] = sre; Xim[i] = sim; }
    __syncthreads();
    float r = 0.f, q = 0.f;
    if (arr == 0) {
#pragma unroll
        for (int ii = 0; ii < 16; ii++) {
            float ar = g_wT[0 * 16384 + f * 256 + ii * 16 + i];
            float ai = g_wT[1 * 16384 + f * 256 + ii * 16 + i];
            r += Dre[ii] * ar - Dim[ii] * ai;
            q += Dre[ii] * ai + Dim[ii] * ar;
            float br = g_wT[2 * 16384 + f * 256 + ii * 16 + i];
            float bi = g_wT[3 * 16384 + f * 256 + ii * 16 + i];
            r += Xre[ii] * br - Xim[ii] * bi;
            q += Xre[ii] * bi + Xim[ii] * br;
        }
    } else {
#pragma unroll
        for (int ii = 0; ii < 16; ii++) {
            float cr = g_wT[4 * 16384 + f * 256 + ii * 16 + i];
            float ci = g_wT[5 * 16384 + f * 256 + ii * 16 + i];
            r += Dre[ii] * cr - Dim[ii] * ci;
            q += Dre[ii] * ci + Dim[ii] * cr;
        }
    }
    float wf = (f == 0) ? (1.0f / (float)m) : (2.0f / (float)m);  // levels 0-5: 2f != m
    size_t o = (((size_t)b * 2 + arr) * 128 + 2 * f) * 16 + i;
    g_spec[o]      = r * wf;
    g_spec[o + 16] = -q * wf;
}

// =================================================================
// inv2: inverse truncated DFT as a 128x128-tile GEMM.
// A[t][k] = (cos,sin) twiddles (shared by all b/arr), B[k][col]=(Re,-Im)*wf.
// block: 128 threads, thread tile 8t x 16cols, grid (m/128, 8).
// =================================================================
__global__ void __launch_bounds__(128) inv2_kernel(float* __restrict__ outUd,
                                                   float* __restrict__ outUs,
                                                   int m, int stride) {
    extern __shared__ float sm[];
    float* sB = sm;              // 128k x 128col = 16384
    float* sA = sB + 16384;      // 2 x 32k x 128t = 8192
    int tid = threadIdx.x;
    int t0 = blockIdx.x * 128;
    int b0 = blockIdx.y * 4;

    // load B (whole K): g_spec[(b0+bl)*4096 + r]
    for (int id = tid; id < 16384; id += 128) {
        int bl = id >> 12, r = id & 4095;
        int arr = r >> 11, r2 = r & 2047;
        int k = r2 >> 4, j = r2 & 15;
        sB[k * 128 + bl * 32 + arr * 16 + j] = g_spec[(size_t)(b0 + bl) * 4096 + r];
    }
    const float2* T2 = (const float2*)g_tabT;
    // stage A chunk st into buffer buf
    auto stageA = [&](int st, int buf) {
        int fbase = st * 16;
#pragma unroll 4
        for (int fp = 0; fp < 16; fp++) {
            float2 cs = T2[(size_t)(fbase + fp) * 8192 + (size_t)(t0 + tid) * stride];
            sA[buf * 4096 + (2 * fp) * 128 + tid]     = cs.x;
            sA[buf * 4096 + (2 * fp + 1) * 128 + tid] = cs.y;
        }
    };
    stageA(0, 0);
    __syncthreads();

    int tg = tid >> 3;           // 0..15 : t rows {tg*4..+3, 64+tg*4..+3}
    int cg = tid & 7;            // cols  {32*jq + cg*4 + jj}
    float acc[8][16];
#pragma unroll
    for (int a = 0; a < 8; a++)
#pragma unroll
        for (int c = 0; c < 16; c++) acc[a][c] = 0.f;

    for (int st = 0; st < 4; st++) {
        int cur = st & 1;
        if (st < 3) stageA(st + 1, cur ^ 1);
        const float* A = &sA[cur * 4096];
        const float* Bst = &sB[st * 32 * 128];   // FIX: global K offset for this chunk
#pragma unroll 2
        for (int k = 0; k < 32; k++) {
            float4 a0 = *(const float4*)&A[k * 128 + tg * 4];
            float4 a1 = *(const float4*)&A[k * 128 + 64 + tg * 4];
            float av[8] = {a0.x, a0.y, a0.z, a0.w, a1.x, a1.y, a1.z, a1.w};
            float bv[16];
#pragma unroll
            for (int jq = 0; jq < 4; jq++) {
                float4 b4 = *(const float4*)&Bst[k * 128 + 32 * jq + cg * 4];
                bv[jq * 4 + 0] = b4.x; bv[jq * 4 + 1] = b4.y;
                bv[jq * 4 + 2] = b4.z; bv[jq * 4 + 3] = b4.w;
            }
#pragma unroll
            for (int a = 0; a < 8; a++)
#pragma unroll
                for (int c = 0; c < 16; c++) acc[a][c] += av[a] * bv[c];
        }
        __syncthreads();
    }
    int arrq = cg >> 2;
    int j0 = (cg & 3) * 4;
    float* outp = arrq ? outUs : outUd;
#pragma unroll
    for (int s = 0; s < 2; s++)
#pragma unroll
        for (int r = 0; r < 4; r++) {
            int t = t0 + s * 64 + tg * 4 + r;
#pragma unroll
            for (int jq = 0; jq < 4; jq++) {
                float4 v = make_float4(acc[s * 4 + r][jq * 4 + 0], acc[s * 4 + r][jq * 4 + 1],
                                       acc[s * 4 + r][jq * 4 + 2], acc[s * 4 + r][jq * 4 + 3]);
                *(float4*)&outp[((size_t)(b0 + jq) * m + t) * 16 + j0] = v;
            }
        }
}

// =================================================================
// deep_kernel: levels 6..13 (m=128..1) entirely in smem, incl. T0
// and reconstruction back up to m=256. One block per batch b.
// =================================================================
__global__ void __launch_bounds__(256, 1) deep_kernel(
        const float* __restrict__ xin, float* __restrict__ xout,
        const float* __restrict__ ecd, const float* __restrict__ ecs,
        const float* __restrict__ rce, const float* __restrict__ rco,
        const float* __restrict__ t0w, const float* __restrict__ t0b) {
    extern __shared__ float dsm[];
    float* X0 = dsm;             // 4096
    float* X1 = X0 + 4096;       // 4096
    float* D  = X1 + 4096;       // 2048
    float* UD = D + 2048;        // 4080
    float* US = UD + 4080;       // 4080
    float* SP = US + 4080;       // 4096  [arr][f][re/im][16]
    float* MS = SP + 4096;       // 4096
    __shared__ float fl[148];
    int b = blockIdx.x, tid = threadIdx.x;
    if (tid < 32)       fl[tid] = ecd[tid];
    else if (tid < 64)  fl[tid] = ecs[tid - 32];
    else if (tid < 96)  fl[tid] = rce[tid - 64];
    else if (tid < 128) fl[tid] = rco[tid - 96];
    else if (tid < 144) fl[tid] = t0w[tid - 128];
    else if (tid < 148) fl[tid] = t0b[tid - 144];
    for (int i = tid; i < 4096; i += 256) X0[i] = xin[(size_t)b * 4096 + i];
    __syncthreads();

    float* xc = X0; float* xn = X1;
    int loff[8];
    int off = 0;
    for (int li = 0; li < 8; li++) { loff[li] = off; off += 128 >> li; }

    // ---------- decomposition chain ----------
    for (int li = 0; li < 8; li++) {
        int m = 128 >> li;
        int stride = 8192 / m;
        // decompose xc(2m) -> D(m), xn(m)
        for (int it = tid; it < m * 4; it += 256) {
            int c = it & 3, s = it >> 2;
            float xa[8];
#pragma unroll
            for (int p = 0; p < 4; p++) {
                xa[p]     = xc[(2 * s) * 16 + c * 4 + p];
                xa[p + 4] = xc[(2 * s + 1) * 16 + c * 4 + p];
            }
            float dv[4] = {0, 0, 0, 0}, sv[4] = {0, 0, 0, 0};
#pragma unroll
            for (int p = 0; p < 8; p++) {
                float xv = xa[p];
#pragma unroll
                for (int j = 0; j < 4; j++) {
                    dv[j] += xv * fl[p * 4 + j];
                    sv[j] += xv * fl[32 + p * 4 + j];
                }
            }
#pragma unroll
            for (int j = 0; j < 4; j++) {
                D[s * 16 + c * 4 + j]  = dv[j];
                xn[s * 16 + c * 4 + j] = sv[j];
            }
        }
        __syncthreads();
        int l = (m / 2 + 1 < 64) ? m / 2 + 1 : 64;
        // forward DFT
        for (int it = tid; it < 2 * l * 16; it += 256) {
            int i = it & 15;
            int f = (it >> 4) % l;
            int arr = it / (16 * l);
            const float* src = arr ? xn : D;
            float re = 0.f, im = 0.f;
            for (int t = 0; t < m; t++) {
                float v = src[t * 16 + i];
                re += v * g_tabc[(t * stride) * 64 + f];
                im -= v * g_tabs[(t * stride) * 64 + f];
            }
            SP[((arr * 64 + f) * 2 + 0) * 16 + i] = re;
            SP[((arr * 64 + f) * 2 + 1) * 16 + i] = im;
        }
        __syncthreads();
        // mixing
        for (int it = tid; it < 2 * l * 16; it += 256) {
            int o = it & 15;
            int f = (it >> 4) % l;
            int arr = it / (16 * l);
            float r = 0.f, q = 0.f;
            if (arr == 0) {
#pragma unroll 4
                for (int i2 = 0; i2 < 16; i2++) {
                    float Dr = SP[((0 * 64 + f) * 2 + 0) * 16 + i2];
                    float Di = SP[((0 * 64 + f) * 2 + 1) * 16 + i2];
                    float Xr = SP[((1 * 64 + f) * 2 + 0) * 16 + i2];
                    float Xi = SP[((1 * 64 + f) * 2 + 1) * 16 + i2];
                    float ar = g_wT[0 * 16384 + f * 256 + i2 * 16 + o];
                    float ai = g_wT[1 * 16384 + f * 256 + i2 * 16 + o];
                    float br = g_wT[2 * 16384 + f * 256 + i2 * 16 + o];
                    float bi = g_wT[3 * 16384 + f * 256 + i2 * 16 + o];
                    r += Dr * ar - Di * ai + Xr * br - Xi * bi;
                    q += Dr * ai + Di * ar + Xr * bi + Xi * br;
                }
            } else {
#pragma unroll 4
                for (int i2 = 0; i2 < 16; i2++) {
                    float Dr = SP[((0 * 64 + f) * 2 + 0) * 16 + i2];
                    float Di = SP[((0 * 64 + f) * 2 + 1) * 16 + i2];
                    float cr = g_wT[4 * 16384 + f * 256 + i2 * 16 + o];
                    float ci = g_wT[5 * 16384 + f * 256 + i2 * 16 + o];
                    r += Dr * cr - Di * ci;
                    q += Dr * ci + Di * cr;
                }
            }
            float wf = (f == 0 || 2 * f == m) ? (1.0f / (float)m) : (2.0f / (float)m);
            MS[((arr * 64 + f) * 2 + 0) * 16 + o] = r * wf;
            MS[((arr * 64 + f) * 2 + 1) * 16 + o] = q * wf;
        }
        __syncthreads();
        // inverse DFT -> UD/US
        for (int it = tid; it < 2 * m * 16; it += 256) {
            int o = it & 15;
            int t = (it >> 4) % m;
            int arr = it / (16 * m);
            float acc = 0.f;
            for (int f = 0; f < l; f++) {
                float r = MS[((arr * 64 + f) * 2 + 0) * 16 + o];
                float q = MS[((arr * 64 + f) * 2 + 1) * 16 + o];
                acc += r * g_tabc[(t * stride) * 64 + f] - q * g_tabs[(t * stride) * 64 + f];
            }
            (arr ? US : UD)[(loff[li] + t) * 16 + o] = acc;
        }
        __syncthreads();
        float* tmp = xc; xc = xn; xn = tmp;
    }
    // ---------- T0 (m=1) ----------
    if (tid < 16) {
        int c = tid >> 2, o = tid & 3;
        float acc = fl[144 + o];
#pragma unroll
        for (int p = 0; p < 4; p++) acc += xc[c * 4 + p] * fl[128 + o * 4 + p];
        xn[tid] = acc;
    }
    __syncthreads();
    { float* tmp = xc; xc = xn; xn = tmp; }
    // ---------- reconstruction chain ----------
    for (int li = 7; li >= 0; li--) {
        int m = 128 >> li;
        for (int it = tid; it < m * 4; it += 256) {
            int c = it & 3, s = it >> 2;
            float xs[4], ud[4];
#pragma unroll
            for (int j = 0; j < 4; j++) {
                xs[j] = xc[s * 16 + c * 4 + j] + US[(loff[li] + s) * 16 + c * 4 + j];
                ud[j] = UD[(loff[li] + s) * 16 + c * 4 + j];
            }
            float e[4] = {0, 0, 0, 0}, o4[4] = {0, 0, 0, 0};
#pragma unroll
            for (int p = 0; p < 4; p++)
#pragma unroll
                for (int j = 0; j < 4; j++) {
                    e[j]  += xs[p] * fl[64 + p * 4 + j] + ud[p] * fl[64 + (p + 4) * 4 + j];
                    o4[j] += xs[p] * fl[96 + p * 4 + j] + ud[p] * fl[96 + (p + 4) * 4 + j];
                }
#pragma unroll
            for (int j = 0; j < 4; j++) {
                xn[(2 * s) * 16 + c * 4 + j]     = e[j];
                xn[(2 * s + 1) * 16 + c * 4 + j] = o4[j];
            }
        }
        __syncthreads();
        float* tmp = xc; xc = xn; xn = tmp;
    }
    for (int i = tid; i < 4096; i += 256) xout[(size_t)b * 4096 + i] = xc[i];
}

// ---------------- reconstruction step (levels 0-5) ----------------
__global__ void recon_kernel(const float* __restrict__ xin, const float* __restrict__ Ud,
                             const float* __restrict__ Us, const float* __restrict__ rce,
                             const float* __restrict__ rco, float* __restrict__ out, int m) {
    __shared__ float se[32], so[32];
    int tid = threadIdx.x;
    if (tid < 32)      se[tid]      = rce[tid];
    else if (tid < 64) so[tid - 32] = rco[tid - 32];
    __syncthreads();
    int idx = blockIdx.x * blockDim.x + tid;
    if (idx >= BB * m * 4) return;
    int c = idx & 3;
    int s = (idx >> 2) % m;
    int b = idx / (m * 4);
    size_t r = ((size_t)b * m + s) * 16 + c * 4;
    float4 xv = *(const float4*)&xin[r];
    float4 uv = *(const float4*)&Us[r];
    float4 dv = *(const float4*)&Ud[r];
    float xs[4] = {xv.x + uv.x, xv.y + uv.y, xv.z + uv.z, xv.w + uv.w};
    float ud[4] = {dv.x, dv.y, dv.z, dv.w};
    float e[4] = {0, 0, 0, 0}, o[4] = {0, 0, 0, 0};
#pragma unroll
    for (int p = 0; p < 4; p++)
#pragma unroll
        for (int j = 0; j < 4; j++) {
            e[j] += xs[p] * se[p * 4 + j] + ud[p] * se[(p + 4) * 4 + j];
            o[j] += xs[p] * so[p * 4 + j] + ud[p] * so[(p + 4) * 4 + j];
        }
    size_t w = ((size_t)b * 2 * m + 2 * s) * 16 + c * 4;
    *(float4*)&out[w]      = make_float4(e[0], e[1], e[2], e[3]);
    *(float4*)&out[w + 16] = make_float4(o[0], o[1], o[2], o[3]);
}

// ---------------- host orchestration ----------------
extern "C" void kernel_launch(void* const* d_in, const int* in_sizes, int n_in,
                              void* d_out, int out_size) {
    const float* x_in = (const float*)d_in[0];
    const float* ec_s = (const float*)d_in[1];
    const float* ec_d = (const float*)d_in[2];
    const float* rc_e = (const float*)d_in[3];
    const float* rc_o = (const float*)d_in[4];
    const float* t0_w = (const float*)d_in[5];
    const float* t0_b = (const float*)d_in[6];

    const int DFWD_SM = (8192 + 4096 + 4096 + 2048 + 2048) * 4;  // 81920
    const int INV_SM  = (16384 + 8192) * 4;                      // 98304
    const int DEEP_SM = (4096 + 4096 + 2048 + 4080 + 4080 + 4096 + 4096) * 4;  // 106368
    cudaFuncSetAttribute(dfwd_kernel, cudaFuncAttributeMaxDynamicSharedMemorySize, DFWD_SM);
    cudaFuncSetAttribute(inv2_kernel, cudaFuncAttributeMaxDynamicSharedMemorySize, INV_SM);
    cudaFuncSetAttribute(deep_kernel, cudaFuncAttributeMaxDynamicSharedMemorySize, DEEP_SM);

    tab_row_kernel<<<2048, 256>>>();
    tab_T_kernel<<<2048, 256>>>();
    wprep_kernel<<<(6 * 16384 + 255) / 256, 256>>>(
        (const float*)d_in[7], (const float*)d_in[8], (const float*)d_in[9],
        (const float*)d_in[10], (const float*)d_in[11], (const float*)d_in[12]);

    float *px0, *px1, *pd, *pUd, *pUs;
    cudaGetSymbolAddress((void**)&px0, g_x0);
    cudaGetSymbolAddress((void**)&px1, g_x1);
    cudaGetSymbolAddress((void**)&pd,  g_d);
    cudaGetSymbolAddress((void**)&pUd, g_Ud);
    cudaGetSymbolAddress((void**)&pUs, g_Us);

    float* xb[2] = {px0, px1};
    size_t offs[6];
    size_t off = 0;
    const float* src = x_in;

    // levels 0..5: fused decompose+fwd, mix, inv
    for (int lev = 0; lev < 6; lev++) {
        int m = NN >> (lev + 1);                 // 8192..256
        offs[lev] = off;
        int stride = MAXM / m;
        int nchunk = m / 128;
        float* xnext = xb[lev & 1];

        dfwd_kernel<<<dim3(4, nchunk), 256, DFWD_SM>>>(src, xnext, ec_d, ec_s, m, stride, nchunk);
        mix_kernel<<<dim3(64, BB), 32>>>(m, nchunk);
        inv2_kernel<<<dim3(m / 128, 8), 128, INV_SM>>>(
            pUd + (size_t)BB * CKD * off, pUs + (size_t)BB * CKD * off, m, stride);

        off += m;
        src = xnext;
    }

    // levels 6..13 + T0 + their reconstruction, all in one kernel
    deep_kernel<<<BB, 256, DEEP_SM>>>(src, pd, ec_d, ec_s, rc_e, rc_o, t0_w, t0_b);

    // reconstruction levels 5..0
    const float* curx = pd;
    int flip = 0;
    for (int lev = 5; lev >= 0; lev--) {
        int m = NN >> (lev + 1);
        float* dst = (lev == 0) ? (float*)d_out : xb[flip];
        int total = BB * m * 4;
        recon_kernel<<<(total + 255) / 256, 256>>>(
            curx, pUd + (size_t)BB * CKD * offs[lev], pUs + (size_t)BB * CKD * offs[lev],
            rc_e, rc_o, dst, m);
        curx = dst;
        flip ^= 1;
    }
}

// round 4
// speedup vs baseline: 1.2239x; 1.2239x over previous
#include <cuda_runtime.h>

#define BB   32
#define NN   16384
#define CKD  16
#define MAXM 8192

// ---------------- device scratch (static, no allocations) ----------------
__device__ __align__(256) float g_x0 [BB*MAXM*CKD];
__device__ __align__(256) float g_x1 [BB*MAXM*CKD];
__device__ __align__(256) float g_d  [BB*MAXM*CKD];     // reused as deep-kernel output
__device__ __align__(256) float g_Ud [BB*(NN-1)*CKD];
__device__ __align__(256) float g_Us [BB*(NN-1)*CKD];
__device__ __align__(256) float g_part[2ull*BB*64*64*CKD*2];
__device__ __align__(256) float g_spec[6ull*BB*4096];   // [lev][b][arr][k=2f(re)/2f+1(-im)][j]
__device__ __align__(256) float g_tabc[MAXM*64];        // [t][f] cos
__device__ __align__(256) float g_tabs[MAXM*64];        // [t][f] sin
__device__ __align__(256) float g_tabT[64*MAXM*2];      // [f][t](cos,sin) interleaved
__device__ __align__(256) float g_wT  [6*64*16*16];     // [arr][f][i][o]

// ---------------- twiddle tables ----------------
__global__ void tab_row_kernel() {
    int idx = blockIdx.x * blockDim.x + threadIdx.x;   // t*64 + f
    int t = idx >> 6, f = idx & 63;
    float ph = (float)(f * t) * (2.0f / 8192.0f);
    float s, c; sincospif(ph, &s, &c);
    g_tabc[idx] = c;
    g_tabs[idx] = s;
}
__global__ void tab_T_kernel() {
    int idx = blockIdx.x * blockDim.x + threadIdx.x;   // f*8192 + t
    int f = idx >> 13, t = idx & 8191;
    float ph = (float)(f * t) * (2.0f / 8192.0f);
    float s, c; sincospif(ph, &s, &c);
    g_tabT[2*idx + 0] = c;
    g_tabT[2*idx + 1] = s;
}

// ---------------- weight transpose: [i][o][f] -> [arr][f][i][o] ----------------
__global__ void wprep_kernel(const float* __restrict__ a0, const float* __restrict__ a1,
                             const float* __restrict__ a2, const float* __restrict__ a3,
                             const float* __restrict__ a4, const float* __restrict__ a5) {
    int idx = blockIdx.x * blockDim.x + threadIdx.x;
    if (idx >= 6*16384) return;
    int arr = idx >> 14;
    int r   = idx & 16383;
    int f = r >> 8, i = (r >> 4) & 15, o = r & 15;
    const float* src = (arr == 0) ? a0 : (arr == 1) ? a1 : (arr == 2) ? a2 :
                       (arr == 3) ? a3 : (arr == 4) ? a4 : a5;
    g_wT[idx] = src[(i * 16 + o) * 64 + f];
}

// =================================================================
// dfwd: fused decompose + forward truncated DFT (split-K partials)
// block: 256 threads = 4 b x (2 i-grp x 16 f-grp x 2 arr).
// thread tile: 8i x 4f, ONE array (d or x) -> 64 accumulators.
// =================================================================
__global__ void __launch_bounds__(256, 2) dfwd_kernel(
        const float* __restrict__ xin, float* __restrict__ xnext,
        const float* __restrict__ ecd, const float* __restrict__ ecs,
        int m, int stride, int nchunk) {
    extern __shared__ float sm[];
    float* s_in = sm;           // 4*64*16 = 4096
    float* s_d  = s_in + 4096;  // 4*32*16 = 2048
    float* s_x  = s_d + 2048;   // 2048
    float* s_tc = s_x + 2048;   // 2048
    float* s_ts = s_tc + 2048;  // 2048  (12288 floats total)
    __shared__ float fl[64];
    int tid = threadIdx.x;
    int b0 = blockIdx.x * 4;
    int ch = blockIdx.y;
    int clen = m / nchunk;      // multiple of 32
    int T0base = ch * clen;
    if (tid < 64) fl[tid] = (tid < 32) ? ecd[tid] : ecs[tid - 32];

    int bloc = tid >> 6;            // 0..3 batch within block
    int sub  = tid & 63;
    int arr  = sub >> 5;            // 0: d, 1: x
    int lane32 = sub & 31;
    int i0 = (lane32 & 1) * 8;
    int f0 = (lane32 >> 1) * 4;
    float aR[8][4] = {}, aI[8][4] = {};

    for (int tb = 0; tb < clen; tb += 32) {
        int T0 = T0base + tb;
        // ---- load 4b x 64 input samples (1024 float4) + 32t x 64f table tile ----
        {
            const float4* gx = (const float4*)xin;
            float4* si = (float4*)s_in;
            for (int id = tid; id < 1024; id += 256) {
                int bl = id >> 8;
                int r  = id & 255;
                si[id] = gx[(((size_t)(b0 + bl) * (2 * m)) + 2 * T0) * 4 + r];
            }
            float4* tc4 = (float4*)s_tc;
            float4* ts4 = (float4*)s_ts;
            for (int id = tid; id < 512; id += 256) {
                int t = id >> 4, q = id & 15;
                size_t g = ((size_t)(T0 + t) * stride) * 16 + q;
                tc4[id] = ((const float4*)g_tabc)[g];
                ts4[id] = ((const float4*)g_tabs)[g];
            }
        }
        __syncthreads();
        // ---- decompose: 4b x 32t x 4c items, also emit x_next to gmem ----
        for (int id = tid; id < 512; id += 256) {
            int c = id & 3, t = (id >> 2) & 31, bl = id >> 7;
            float xa[8];
#pragma unroll
            for (int p = 0; p < 4; p++) {
                xa[p]     = s_in[(bl * 64 + 2 * t) * 16 + c * 4 + p];
                xa[p + 4] = s_in[(bl * 64 + 2 * t + 1) * 16 + c * 4 + p];
            }
            float dv[4] = {0, 0, 0, 0}, sv[4] = {0, 0, 0, 0};
#pragma unroll
            for (int p = 0; p < 8; p++) {
                float xv = xa[p];
#pragma unroll
                for (int j = 0; j < 4; j++) {
                    dv[j] += xv * fl[p * 4 + j];
                    sv[j] += xv * fl[32 + p * 4 + j];
                }
            }
            float4 d4 = make_float4(dv[0], dv[1], dv[2], dv[3]);
            float4 s4 = make_float4(sv[0], sv[1], sv[2], sv[3]);
            *(float4*)&s_d[(bl * 32 + t) * 16 + c * 4] = d4;
            *(float4*)&s_x[(bl * 32 + t) * 16 + c * 4] = s4;
            *(float4*)&xnext[(((size_t)(b0 + bl) * m) + T0 + t) * 16 + c * 4] = s4;
        }
        __syncthreads();
        // ---- DFT accumulation ----
        const float* sdx = arr ? s_x : s_d;
#pragma unroll 4
        for (int tt = 0; tt < 32; tt++) {
            const float* bd = &sdx[(bloc * 32 + tt) * 16];
            float4 d0 = *(const float4*)&bd[i0];
            float4 d1 = *(const float4*)&bd[i0 + 4];
            float4 cv = *(const float4*)&s_tc[tt * 64 + f0];
            float4 sv = *(const float4*)&s_ts[tt * 64 + f0];
            float dd[8] = {d0.x, d0.y, d0.z, d0.w, d1.x, d1.y, d1.z, d1.w};
            float cf[4] = {cv.x, cv.y, cv.z, cv.w};
            float sf[4] = {sv.x, sv.y, sv.z, sv.w};
#pragma unroll
            for (int ii = 0; ii < 8; ii++)
#pragma unroll
                for (int ff = 0; ff < 4; ff++) {
                    aR[ii][ff] += dd[ii] * cf[ff];
                    aI[ii][ff] -= dd[ii] * sf[ff];
                }
        }
        __syncthreads();
    }
    // ---- write partials ----
    float2* P = (float2*)g_part;
    int b = b0 + bloc;
    size_t base = (((size_t)arr * BB + b) * nchunk + ch) * 64;
#pragma unroll
    for (int ff = 0; ff < 4; ff++)
#pragma unroll
        for (int ii = 0; ii < 8; ii++)
            P[(base + f0 + ff) * 16 + i0 + ii] = make_float2(aR[ii][ff], aI[ii][ff]);
}

// ---------------- reduce partials + mixing + irfft weighting (Im negated) ----------------
__global__ void mix_kernel(int m, int nchunk, int lev) {
    int f = blockIdx.x;
    int b = blockIdx.y;
    int tid = threadIdx.x;          // 32 threads
    __shared__ float Dre[16], Dim[16], Xre[16], Xim[16];
    int arr = tid >> 4, i = tid & 15;
    const float2* P = (const float2*)g_part;
    float sre = 0.f, sim = 0.f;
    size_t base = (((size_t)arr * BB + b) * nchunk) * 64 + f;
    for (int ch = 0; ch < nchunk; ch++) {
        float2 p = P[(base + (size_t)ch * 64) * 16 + i];
        sre += p.x; sim += p.y;
    }
    if (arr == 0) { Dre[i] = sre; Dim[i] = sim; }
    else          { Xre[i] = sre; Xim[i] = sim; }
    __syncthreads();
    float r = 0.f, q = 0.f;
    if (arr == 0) {
#pragma unroll
        for (int ii = 0; ii < 16; ii++) {
            float ar = g_wT[0 * 16384 + f * 256 + ii * 16 + i];
            float ai = g_wT[1 * 16384 + f * 256 + ii * 16 + i];
            r += Dre[ii] * ar - Dim[ii] * ai;
            q += Dre[ii] * ai + Dim[ii] * ar;
            float br = g_wT[2 * 16384 + f * 256 + ii * 16 + i];
            float bi = g_wT[3 * 16384 + f * 256 + ii * 16 + i];
            r += Xre[ii] * br - Xim[ii] * bi;
            q += Xre[ii] * bi + Xim[ii] * br;
        }
    } else {
#pragma unroll
        for (int ii = 0; ii < 16; ii++) {
            float cr = g_wT[4 * 16384 + f * 256 + ii * 16 + i];
            float ci = g_wT[5 * 16384 + f * 256 + ii * 16 + i];
            r += Dre[ii] * cr - Dim[ii] * ci;
            q += Dre[ii] * ci + Dim[ii] * cr;
        }
    }
    float wf = (f == 0) ? (1.0f / (float)m) : (2.0f / (float)m);  // levels 0-5: 2f != m
    size_t o = (size_t)lev * BB * 4096 + (((size_t)b * 2 + arr) * 128 + 2 * f) * 16 + i;
    g_spec[o]      = r * wf;
    g_spec[o + 16] = -q * wf;
}

// ---------------- Nyquist sample y[m/2] for all 6 shallow levels ----------------
__global__ void nyq_kernel(float* __restrict__ pUd, float* __restrict__ pUs) {
    const int ms[6]   = {8192, 4096, 2048, 1024, 512, 256};
    const int offs[6] = {0, 8192, 12288, 14336, 15360, 15872};
    int lev = blockIdx.x, b = blockIdx.y;
    int tid = threadIdx.x;           // 32 = 16 j x 2 arr
    int arr = tid >> 4, j = tid & 15;
    int m = ms[lev];
    const float* sp = g_spec + (size_t)lev * BB * 4096 + ((size_t)b * 2 + arr) * 2048;
    float acc = 0.f;
#pragma unroll
    for (int f = 0; f < 64; f += 2) acc += sp[32 * f + j];       // rows k=2f hold re*wf
#pragma unroll
    for (int f = 1; f < 64; f += 2) acc -= sp[32 * f + j];
    float* out = (arr ? pUs : pUd) + (size_t)BB * CKD * offs[lev];
    out[((size_t)b * m + m / 2) * 16 + j] = acc;
}

// =================================================================
// inv2: inverse truncated DFT with conjugate symmetry.
// Block covers 32 t-pairs (t, m-t) x 128 cols (4b x 2arr x 16j).
// u = sum re*wf*cos, v = sum (-im*wf)*sin; y[t]=u+v, y[m-t]=u-v.
// thread: 4 t-pairs x 8 cols x (u,v) = 64 acc. grid (m/64, 8).
// =================================================================
__global__ void __launch_bounds__(128, 3) inv2_kernel(float* __restrict__ outUd,
                                                      float* __restrict__ outUs,
                                                      int m, int stride, int lev) {
    extern __shared__ float sm[];
    float* sB = sm;              // 128 k x 128 col = 16384
    float* sA = sB + 16384;      // 2 buf x (32 rows x 32 t) = 2048
    int tid = threadIdx.x;
    int t0 = blockIdx.x * 32;    // t in [t0, t0+32) < m/2
    int b0 = blockIdx.y * 4;

    // load B: spec for 4 batches, both arrays
    const float4* spec4 = (const float4*)g_spec + (size_t)lev * BB * 1024;
    float4* sB4 = (float4*)sB;
    for (int id = tid; id < 4096; id += 128) {
        int k = id >> 5, col4 = id & 31;
        int bl = col4 >> 3, arr = (col4 >> 2) & 1, j4 = col4 & 3;
        sB4[id] = spec4[(((size_t)(b0 + bl) * 2 + arr) * 128 + k) * 4 + j4];
    }
    const float2* T2 = (const float2*)g_tabT;
    int tl = tid & 31;
    int fq = tid >> 5;   // 0..3
    auto stageA = [&](int st, int buf) {
#pragma unroll
        for (int q = 0; q < 4; q++) {
            int fp = fq * 4 + q;                 // local f 0..15
            int f = st * 16 + fp;
            float2 cs = T2[(size_t)f * 8192 + (size_t)(t0 + tl) * stride];
            sA[buf * 1024 + (2 * fp) * 32 + tl]     = cs.x;
            sA[buf * 1024 + (2 * fp + 1) * 32 + tl] = cs.y;
        }
    };
    stageA(0, 0);
    __syncthreads();

    int cg = tid & 15;   // col group: cols cg*8..cg*8+7
    int tg = tid >> 4;   // 0..7: t-pairs t0 + tg*4 + r
    float u[4][8] = {}, v[4][8] = {};

    for (int st = 0; st < 4; st++) {
        int cur = st & 1;
        if (st < 3) stageA(st + 1, cur ^ 1);
        const float* A = &sA[cur * 1024];
        const float* Bst = &sB[st * 32 * 128];
#pragma unroll 4
        for (int fp = 0; fp < 16; fp++) {
            float4 ac = *(const float4*)&A[(2 * fp) * 32 + tg * 4];
            float4 as = *(const float4*)&A[(2 * fp + 1) * 32 + tg * 4];
            float4 bu0 = *(const float4*)&Bst[(2 * fp) * 128 + cg * 8];
            float4 bu1 = *(const float4*)&Bst[(2 * fp) * 128 + cg * 8 + 4];
            float4 bv0 = *(const float4*)&Bst[(2 * fp + 1) * 128 + cg * 8];
            float4 bv1 = *(const float4*)&Bst[(2 * fp + 1) * 128 + cg * 8 + 4];
            float acv[4] = {ac.x, ac.y, ac.z, ac.w};
            float asv[4] = {as.x, as.y, as.z, as.w};
            float buv[8] = {bu0.x, bu0.y, bu0.z, bu0.w, bu1.x, bu1.y, bu1.z, bu1.w};
            float bvv[8] = {bv0.x, bv0.y, bv0.z, bv0.w, bv1.x, bv1.y, bv1.z, bv1.w};
#pragma unroll
            for (int r = 0; r < 4; r++)
#pragma unroll
                for (int c = 0; c < 8; c++) {
                    u[r][c] += acv[r] * buv[c];
                    v[r][c] += asv[r] * bvv[c];
                }
        }
        __syncthreads();
    }
    int bl = cg >> 2, arr = (cg >> 1) & 1, j0 = (cg & 1) * 8;
    float* outp = (arr ? outUs : outUd) + ((size_t)(b0 + bl) * m) * 16 + j0;
#pragma unroll
    for (int r = 0; r < 4; r++) {
        int t = t0 + tg * 4 + r;
        float4 y0 = make_float4(u[r][0] + v[r][0], u[r][1] + v[r][1],
                                u[r][2] + v[r][2], u[r][3] + v[r][3]);
        float4 y1 = make_float4(u[r][4] + v[r][4], u[r][5] + v[r][5],
                                u[r][6] + v[r][6], u[r][7] + v[r][7]);
        *(float4*)&outp[(size_t)t * 16]     = y0;
        *(float4*)&outp[(size_t)t * 16 + 4] = y1;
        if (t > 0) {
            size_t tm = (size_t)(m - t);
            float4 z0 = make_float4(u[r][0] - v[r][0], u[r][1] - v[r][1],
                                    u[r][2] - v[r][2], u[r][3] - v[r][3]);
            float4 z1 = make_float4(u[r][4] - v[r][4], u[r][5] - v[r][5],
                                    u[r][6] - v[r][6], u[r][7] - v[r][7]);
            *(float4*)&outp[tm * 16]     = z0;
            *(float4*)&outp[tm * 16 + 4] = z1;
        }
    }
}

// =================================================================
// deep_kernel: levels 6..13 (m=128..1) entirely in smem, incl. T0
// and reconstruction back up to m=256. One block per batch b.
// =================================================================
__global__ void __launch_bounds__(256, 1) deep_kernel(
        const float* __restrict__ xin, float* __restrict__ xout,
        const float* __restrict__ ecd, const float* __restrict__ ecs,
        const float* __restrict__ rce, const float* __restrict__ rco,
        const float* __restrict__ t0w, const float* __restrict__ t0b) {
    extern __shared__ float dsm[];
    float* X0 = dsm;             // 4096
    float* X1 = X0 + 4096;       // 4096
    float* D  = X1 + 4096;       // 2048
    float* UD = D + 2048;        // 4080
    float* US = UD + 4080;       // 4080
    float* SP = US + 4080;       // 4096
    float* MS = SP + 4096;       // 4096
    __shared__ float fl[148];
    int b = blockIdx.x, tid = threadIdx.x;
    if (tid < 32)       fl[tid] = ecd[tid];
    else if (tid < 64)  fl[tid] = ecs[tid - 32];
    else if (tid < 96)  fl[tid] = rce[tid - 64];
    else if (tid < 128) fl[tid] = rco[tid - 96];
    else if (tid < 144) fl[tid] = t0w[tid - 128];
    else if (tid < 148) fl[tid] = t0b[tid - 144];
    for (int i = tid; i < 4096; i += 256) X0[i] = xin[(size_t)b * 4096 + i];
    __syncthreads();

    float* xc = X0; float* xn = X1;
    int loff[8];
    int off = 0;
    for (int li = 0; li < 8; li++) { loff[li] = off; off += 128 >> li; }

    for (int li = 0; li < 8; li++) {
        int m = 128 >> li;
        int stride = 8192 / m;
        for (int it = tid; it < m * 4; it += 256) {
            int c = it & 3, s = it >> 2;
            float xa[8];
#pragma unroll
            for (int p = 0; p < 4; p++) {
                xa[p]     = xc[(2 * s) * 16 + c * 4 + p];
                xa[p + 4] = xc[(2 * s + 1) * 16 + c * 4 + p];
            }
            float dv[4] = {0, 0, 0, 0}, sv[4] = {0, 0, 0, 0};
#pragma unroll
            for (int p = 0; p < 8; p++) {
                float xv = xa[p];
#pragma unroll
                for (int j = 0; j < 4; j++) {
                    dv[j] += xv * fl[p * 4 + j];
                    sv[j] += xv * fl[32 + p * 4 + j];
                }
            }
#pragma unroll
            for (int j = 0; j < 4; j++) {
                D[s * 16 + c * 4 + j]  = dv[j];
                xn[s * 16 + c * 4 + j] = sv[j];
            }
        }
        __syncthreads();
        int l = (m / 2 + 1 < 64) ? m / 2 + 1 : 64;
        for (int it = tid; it < 2 * l * 16; it += 256) {
            int i = it & 15;
            int f = (it >> 4) % l;
            int arr = it / (16 * l);
            const float* src = arr ? xn : D;
            float re = 0.f, im = 0.f;
            for (int t = 0; t < m; t++) {
                float v = src[t * 16 + i];
                re += v * g_tabc[(t * stride) * 64 + f];
                im -= v * g_tabs[(t * stride) * 64 + f];
            }
            SP[((arr * 64 + f) * 2 + 0) * 16 + i] = re;
            SP[((arr * 64 + f) * 2 + 1) * 16 + i] = im;
        }
        __syncthreads();
        for (int it = tid; it < 2 * l * 16; it += 256) {
            int o = it & 15;
            int f = (it >> 4) % l;
            int arr = it / (16 * l);
            float r = 0.f, q = 0.f;
            if (arr == 0) {
#pragma unroll 4
                for (int i2 = 0; i2 < 16; i2++) {
                    float Dr = SP[((0 * 64 + f) * 2 + 0) * 16 + i2];
                    float Di = SP[((0 * 64 + f) * 2 + 1) * 16 + i2];
                    float Xr = SP[((1 * 64 + f) * 2 + 0) * 16 + i2];
                    float Xi = SP[((1 * 64 + f) * 2 + 1) * 16 + i2];
                    float ar = g_wT[0 * 16384 + f * 256 + i2 * 16 + o];
                    float ai = g_wT[1 * 16384 + f * 256 + i2 * 16 + o];
                    float br = g_wT[2 * 16384 + f * 256 + i2 * 16 + o];
                    float bi = g_wT[3 * 16384 + f * 256 + i2 * 16 + o];
                    r += Dr * ar - Di * ai + Xr * br - Xi * bi;
                    q += Dr * ai + Di * ar + Xr * bi + Xi * br;
                }
            } else {
#pragma unroll 4
                for (int i2 = 0; i2 < 16; i2++) {
                    float Dr = SP[((0 * 64 + f) * 2 + 0) * 16 + i2];
                    float Di = SP[((0 * 64 + f) * 2 + 1) * 16 + i2];
                    float cr = g_wT[4 * 16384 + f * 256 + i2 * 16 + o];
                    float ci = g_wT[5 * 16384 + f * 256 + i2 * 16 + o];
                    r += Dr * cr - Di * ci;
                    q += Dr * ci + Di * cr;
                }
            }
            float wf = (f == 0 || 2 * f == m) ? (1.0f / (float)m) : (2.0f / (float)m);
            MS[((arr * 64 + f) * 2 + 0) * 16 + o] = r * wf;
            MS[((arr * 64 + f) * 2 + 1) * 16 + o] = q * wf;
        }
        __syncthreads();
        for (int it = tid; it < 2 * m * 16; it += 256) {
            int o = it & 15;
            int t = (it >> 4) % m;
            int arr = it / (16 * m);
            float acc = 0.f;
            for (int f = 0; f < l; f++) {
                float r = MS[((arr * 64 + f) * 2 + 0) * 16 + o];
                float q = MS[((arr * 64 + f) * 2 + 1) * 16 + o];
                acc += r * g_tabc[(t * stride) * 64 + f] - q * g_tabs[(t * stride) * 64 + f];
            }
            (arr ? US : UD)[(loff[li] + t) * 16 + o] = acc;
        }
        __syncthreads();
        float* tmp = xc; xc = xn; xn = tmp;
    }
    if (tid < 16) {
        int c = tid >> 2, o = tid & 3;
        float acc = fl[144 + o];
#pragma unroll
        for (int p = 0; p < 4; p++) acc += xc[c * 4 + p] * fl[128 + o * 4 + p];
        xn[tid] = acc;
    }
    __syncthreads();
    { float* tmp = xc; xc = xn; xn = tmp; }
    for (int li = 7; li >= 0; li--) {
        int m = 128 >> li;
        for (int it = tid; it < m * 4; it += 256) {
            int c = it & 3, s = it >> 2;
            float xs[4], ud[4];
#pragma unroll
            for (int j = 0; j < 4; j++) {
                xs[j] = xc[s * 16 + c * 4 + j] + US[(loff[li] + s) * 16 + c * 4 + j];
                ud[j] = UD[(loff[li] + s) * 16 + c * 4 + j];
            }
            float e[4] = {0, 0, 0, 0}, o4[4] = {0, 0, 0, 0};
#pragma unroll
            for (int p = 0; p < 4; p++)
#pragma unroll
                for (int j = 0; j < 4; j++) {
                    e[j]  += xs[p] * fl[64 + p * 4 + j] + ud[p] * fl[64 + (p + 4) * 4 + j];
                    o4[j] += xs[p] * fl[96 + p * 4 + j] + ud[p] * fl[96 + (p + 4) * 4 + j];
                }
#pragma unroll
            for (int j = 0; j < 4; j++) {
                xn[(2 * s) * 16 + c * 4 + j]     = e[j];
                xn[(2 * s + 1) * 16 + c * 4 + j] = o4[j];
            }
        }
        __syncthreads();
        float* tmp = xc; xc = xn; xn = tmp;
    }
    for (int i = tid; i < 4096; i += 256) xout[(size_t)b * 4096 + i] = xc[i];
}

// ---------------- reconstruction step (levels 0-5) ----------------
__global__ void recon_kernel(const float* __restrict__ xin, const float* __restrict__ Ud,
                             const float* __restrict__ Us, const float* __restrict__ rce,
                             const float* __restrict__ rco, float* __restrict__ out, int m) {
    __shared__ float se[32], so[32];
    int tid = threadIdx.x;
    if (tid < 32)      se[tid]      = rce[tid];
    else if (tid < 64) so[tid - 32] = rco[tid - 32];
    __syncthreads();
    int idx = blockIdx.x * blockDim.x + tid;
    if (idx >= BB * m * 4) return;
    int c = idx & 3;
    int s = (idx >> 2) % m;
    int b = idx / (m * 4);
    size_t r = ((size_t)b * m + s) * 16 + c * 4;
    float4 xv = *(const float4*)&xin[r];
    float4 uv = *(const float4*)&Us[r];
    float4 dv = *(const float4*)&Ud[r];
    float xs[4] = {xv.x + uv.x, xv.y + uv.y, xv.z + uv.z, xv.w + uv.w};
    float ud[4] = {dv.x, dv.y, dv.z, dv.w};
    float e[4] = {0, 0, 0, 0}, o[4] = {0, 0, 0, 0};
#pragma unroll
    for (int p = 0; p < 4; p++)
#pragma unroll
        for (int j = 0; j < 4; j++) {
            e[j] += xs[p] * se[p * 4 + j] + ud[p] * se[(p + 4) * 4 + j];
            o[j] += xs[p] * so[p * 4 + j] + ud[p] * so[(p + 4) * 4 + j];
        }
    size_t w = ((size_t)b * 2 * m + 2 * s) * 16 + c * 4;
    *(float4*)&out[w]      = make_float4(e[0], e[1], e[2], e[3]);
    *(float4*)&out[w + 16] = make_float4(o[0], o[1], o[2], o[3]);
}

// ---------------- host orchestration ----------------
extern "C" void kernel_launch(void* const* d_in, const int* in_sizes, int n_in,
                              void* d_out, int out_size) {
    const float* x_in = (const float*)d_in[0];
    const float* ec_s = (const float*)d_in[1];
    const float* ec_d = (const float*)d_in[2];
    const float* rc_e = (const float*)d_in[3];
    const float* rc_o = (const float*)d_in[4];
    const float* t0_w = (const float*)d_in[5];
    const float* t0_b = (const float*)d_in[6];

    const int DFWD_SM = 12288 * 4;                   // 49152
    const int INV_SM  = (16384 + 2048) * 4;          // 73728
    const int DEEP_SM = (4096 + 4096 + 2048 + 4080 + 4080 + 4096 + 4096) * 4;
    cudaFuncSetAttribute(dfwd_kernel, cudaFuncAttributeMaxDynamicSharedMemorySize, DFWD_SM);
    cudaFuncSetAttribute(inv2_kernel, cudaFuncAttributeMaxDynamicSharedMemorySize, INV_SM);
    cudaFuncSetAttribute(deep_kernel, cudaFuncAttributeMaxDynamicSharedMemorySize, DEEP_SM);

    tab_row_kernel<<<2048, 256>>>();
    tab_T_kernel<<<2048, 256>>>();
    wprep_kernel<<<(6 * 16384 + 255) / 256, 256>>>(
        (const float*)d_in[7], (const float*)d_in[8], (const float*)d_in[9],
        (const float*)d_in[10], (const float*)d_in[11], (const float*)d_in[12]);

    float *px0, *px1, *pd, *pUd, *pUs;
    cudaGetSymbolAddress((void**)&px0, g_x0);
    cudaGetSymbolAddress((void**)&px1, g_x1);
    cudaGetSymbolAddress((void**)&pd,  g_d);
    cudaGetSymbolAddress((void**)&pUd, g_Ud);
    cudaGetSymbolAddress((void**)&pUs, g_Us);

    float* xb[2] = {px0, px1};
    size_t offs[6];
    size_t off = 0;
    const float* src = x_in;

    // levels 0..5: fused decompose+fwd, mix, symmetric inverse
    for (int lev = 0; lev < 6; lev++) {
        int m = NN >> (lev + 1);                 // 8192..256
        offs[lev] = off;
        int stride = MAXM / m;
        int nchunk = (lev == 0) ? 32 : m / 128;  // clen 256 for lvl0, else 128
        float* xnext = xb[lev & 1];

        dfwd_kernel<<<dim3(8, nchunk), 256, DFWD_SM>>>(src, xnext, ec_d, ec_s, m, stride, nchunk);
        mix_kernel<<<dim3(64, BB), 32>>>(m, nchunk, lev);
        inv2_kernel<<<dim3(m / 64, 8), 128, INV_SM>>>(
            pUd + (size_t)BB * CKD * off, pUs + (size_t)BB * CKD * off, m, stride, lev);

        off += m;
        src = xnext;
    }

    // Nyquist samples y[m/2] for all 6 levels
    nyq_kernel<<<dim3(6, BB), 32>>>(pUd, pUs);

    // levels 6..13 + T0 + their reconstruction, all in one kernel
    deep_kernel<<<BB, 256, DEEP_SM>>>(src, pd, ec_d, ec_s, rc_e, rc_o, t0_w, t0_b);

    // reconstruction levels 5..0
    const float* curx = pd;
    int flip = 0;
    for (int lev = 5; lev >= 0; lev--) {
        int m = NN >> (lev + 1);
        float* dst = (lev == 0) ? (float*)d_out : xb[flip];
        int total = BB * m * 4;
        recon_kernel<<<(total + 255) / 256, 256>>>(
            curx, pUd + (size_t)BB * CKD * offs[lev], pUs + (size_t)BB * CKD * offs[lev],
            rc_e, rc_o, dst, m);
        curx = dst;
        flip ^= 1;
    }
}

// round 6
// speedup vs baseline: 1.2503x; 1.0216x over previous
#include <cuda_runtime.h>

#define BB   32
#define NN   16384
#define CKD  16
#define MAXM 8192

// ---------------- device scratch (static, no allocations) ----------------
__device__ __align__(256) float g_x0 [BB*MAXM*CKD];
__device__ __align__(256) float g_x1 [BB*MAXM*CKD];
__device__ __align__(256) float g_d  [BB*MAXM*CKD];     // reused as deep-kernel output
__device__ __align__(256) float g_Ud [BB*(NN-1)*CKD];
__device__ __align__(256) float g_Us [BB*(NN-1)*CKD];
__device__ __align__(256) float g_part[2ull*BB*64*64*CKD*2];
__device__ __align__(256) float g_spec[6ull*BB*4096];   // [lev][b][arr][k=2f(re)/2f+1(-im)][j]
__device__ __align__(256) float g_edge[BB*32];          // [b][d0(16) | dmh(16)]
__device__ __align__(256) float g_tabc[MAXM*64];        // [t][f] cos
__device__ __align__(256) float g_tabs[MAXM*64];        // [t][f] sin
__device__ __align__(256) float g_tabT[64*MAXM*2];      // [f][t](cos,sin) interleaved
__device__ __align__(256) float g_wT  [6*64*16*16];     // [arr][f][i][o]

// ---------------- twiddle tables ----------------
__global__ void tab_row_kernel() {
    int idx = blockIdx.x * blockDim.x + threadIdx.x;   // t*64 + f
    int t = idx >> 6, f = idx & 63;
    float ph = (float)(f * t) * (2.0f / 8192.0f);
    float s, c; sincospif(ph, &s, &c);
    g_tabc[idx] = c;
    g_tabs[idx] = s;
}
__global__ void tab_T_kernel() {
    int idx = blockIdx.x * blockDim.x + threadIdx.x;   // f*8192 + t
    int f = idx >> 13, t = idx & 8191;
    float ph = (float)(f * t) * (2.0f / 8192.0f);
    float s, c; sincospif(ph, &s, &c);
    g_tabT[2*idx + 0] = c;
    g_tabT[2*idx + 1] = s;
}

// ---------------- weight transpose: [i][o][f] -> [arr][f][i][o] ----------------
__global__ void wprep_kernel(const float* __restrict__ a0, const float* __restrict__ a1,
                             const float* __restrict__ a2, const float* __restrict__ a3,
                             const float* __restrict__ a4, const float* __restrict__ a5) {
    int idx = blockIdx.x * blockDim.x + threadIdx.x;
    if (idx >= 6*16384) return;
    int arr = idx >> 14;
    int r   = idx & 16383;
    int f = r >> 8, i = (r >> 4) & 15, o = r & 15;
    const float* src = (arr == 0) ? a0 : (arr == 1) ? a1 : (arr == 2) ? a2 :
                       (arr == 3) ? a3 : (arr == 4) ? a4 : a5;
    g_wT[idx] = src[(i * 16 + o) * 64 + f];
}

// =================================================================
// dfwd: fused decompose + FOLDED forward truncated DFT.
// Covers s in [0, m/2) plus mirrored samples m-s. Fold:
//   p = d_s + d_{m-s}, q = d_s - d_{m-s}
//   Re_f = sum p cos(fs), Im_f = -sum q sin(fs)   (s=0, m/2 -> edge buf)
// block: 256 threads = 4 b x (2 i-grp x 16 f-grp x 2 arr).
// =================================================================
__global__ void __launch_bounds__(256, 2) dfwd_kernel(
        const float* __restrict__ xin, float* __restrict__ xnext,
        const float* __restrict__ ecd, const float* __restrict__ ecs,
        int m, int stride, int nchunk) {
    extern __shared__ float sm[];
    float* s_dp = sm;            // 4*32*16 = 2048
    float* s_dq = s_dp + 2048;   // 2048
    float* s_xp = s_dq + 2048;   // 2048
    float* s_xq = s_xp + 2048;   // 2048
    float* s_tc = s_xq + 2048;   // 2048
    float* s_ts = s_tc + 2048;   // 2048  (12288 floats)
    __shared__ float fl[64];
    int tid = threadIdx.x;
    int b0 = blockIdx.x * 4;
    int ch = blockIdx.y;
    int clen = (m / 2) / nchunk;      // multiple of 32
    int T0base = ch * clen;
    if (tid < 64) fl[tid] = (tid < 32) ? ecd[tid] : ecs[tid - 32];
    __syncthreads();   // RACE FIX: fl must be visible before decompose reads it

    int bloc = tid >> 6;            // 0..3 batch within block
    int sub  = tid & 63;
    int arr  = sub >> 5;            // 0: d, 1: x
    int lane32 = sub & 31;
    int i0 = (lane32 & 1) * 8;
    int f0 = (lane32 >> 1) * 4;
    float aR[8][4] = {}, aI[8][4] = {};

    for (int tb = 0; tb < clen; tb += 32) {
        int T0 = T0base + tb;
        // ---- twiddle tile: rows s = T0..T0+31 ----
        {
            float4* tc4 = (float4*)s_tc;
            float4* ts4 = (float4*)s_ts;
            for (int id = tid; id < 512; id += 256) {
                int t = id >> 4, q = id & 15;
                size_t g = ((size_t)(T0 + t) * stride) * 16 + q;
                tc4[id] = ((const float4*)g_tabc)[g];
                ts4[id] = ((const float4*)g_tabs)[g];
            }
        }
        // ---- decompose fwd + mirror, fold into p/q, emit xnext ----
        for (int id = tid; id < 512; id += 256) {
            int c = id & 3, t = (id >> 2) & 31, bl = id >> 7;
            int s = T0 + t;
            int smir = (s == 0) ? (m >> 1) : (m - s);
            size_t brow = (size_t)(b0 + bl) * (2 * m);
            float4 F0 = *(const float4*)&xin[(brow + 2 * s) * 16 + c * 4];
            float4 F1 = *(const float4*)&xin[(brow + 2 * s + 1) * 16 + c * 4];
            float4 M0 = *(const float4*)&xin[(brow + 2 * smir) * 16 + c * 4];
            float4 M1 = *(const float4*)&xin[(brow + 2 * smir + 1) * 16 + c * 4];
            float xf[8] = {F0.x, F0.y, F0.z, F0.w, F1.x, F1.y, F1.z, F1.w};
            float xm[8] = {M0.x, M0.y, M0.z, M0.w, M1.x, M1.y, M1.z, M1.w};
            float df[4] = {0,0,0,0}, sf[4] = {0,0,0,0};
            float dm[4] = {0,0,0,0}, smv[4] = {0,0,0,0};
#pragma unroll
            for (int p = 0; p < 8; p++) {
                float a = xf[p], bvv = xm[p];
#pragma unroll
                for (int j = 0; j < 4; j++) {
                    df[j]  += a * fl[p * 4 + j];
                    sf[j]  += a * fl[32 + p * 4 + j];
                    dm[j]  += bvv * fl[p * 4 + j];
                    smv[j] += bvv * fl[32 + p * 4 + j];
                }
            }
            size_t bnext = (size_t)(b0 + bl) * m;
            *(float4*)&xnext[(bnext + s) * 16 + c * 4]    = make_float4(sf[0], sf[1], sf[2], sf[3]);
            *(float4*)&xnext[(bnext + smir) * 16 + c * 4] = make_float4(smv[0], smv[1], smv[2], smv[3]);
            float pd[4], qd[4], px[4], qx[4];
            if (s == 0) {
                // edge: d0 and d_{m/2} to side buffer; excluded from fold sums
                *(float4*)&g_edge[(b0 + bl) * 32 + c * 4]      = make_float4(df[0], df[1], df[2], df[3]);
                *(float4*)&g_edge[(b0 + bl) * 32 + 16 + c * 4] = make_float4(dm[0], dm[1], dm[2], dm[3]);
#pragma unroll
                for (int j = 0; j < 4; j++) { pd[j]=0.f; qd[j]=0.f; px[j]=0.f; qx[j]=0.f; }
            } else {
#pragma unroll
                for (int j = 0; j < 4; j++) {
                    pd[j] = df[j] + dm[j];  qd[j] = df[j] - dm[j];
                    px[j] = sf[j] + smv[j]; qx[j] = sf[j] - smv[j];
                }
            }
            int soff = (bl * 32 + t) * 16 + c * 4;
            *(float4*)&s_dp[soff] = make_float4(pd[0], pd[1], pd[2], pd[3]);
            *(float4*)&s_dq[soff] = make_float4(qd[0], qd[1], qd[2], qd[3]);
            *(float4*)&s_xp[soff] = make_float4(px[0], px[1], px[2], px[3]);
            *(float4*)&s_xq[soff] = make_float4(qx[0], qx[1], qx[2], qx[3]);
        }
        __syncthreads();
        // ---- folded DFT accumulation ----
        const float* sp = arr ? s_xp : s_dp;
        const float* sq = arr ? s_xq : s_dq;
#pragma unroll 4
        for (int tt = 0; tt < 32; tt++) {
            int base = (bloc * 32 + tt) * 16;
            float4 p0 = *(const float4*)&sp[base + i0];
            float4 p1 = *(const float4*)&sp[base + i0 + 4];
            float4 q0 = *(const float4*)&sq[base + i0];
            float4 q1 = *(const float4*)&sq[base + i0 + 4];
            float4 cv = *(const float4*)&s_tc[tt * 64 + f0];
            float4 sv = *(const float4*)&s_ts[tt * 64 + f0];
            float pp[8] = {p0.x, p0.y, p0.z, p0.w, p1.x, p1.y, p1.z, p1.w};
            float qq[8] = {q0.x, q0.y, q0.z, q0.w, q1.x, q1.y, q1.z, q1.w};
            float cf[4] = {cv.x, cv.y, cv.z, cv.w};
            float sff[4] = {sv.x, sv.y, sv.z, sv.w};
#pragma unroll
            for (int ii = 0; ii < 8; ii++)
#pragma unroll
                for (int ff = 0; ff < 4; ff++) {
                    aR[ii][ff] += pp[ii] * cf[ff];
                    aI[ii][ff] -= qq[ii] * sff[ff];
                }
        }
        __syncthreads();
    }
    // ---- write partials ----
    float2* P = (float2*)g_part;
    int b = b0 + bloc;
    size_t base = (((size_t)arr * BB + b) * nchunk + ch) * 64;
#pragma unroll
    for (int ff = 0; ff < 4; ff++)
#pragma unroll
        for (int ii = 0; ii < 8; ii++)
            P[(base + f0 + ff) * 16 + i0 + ii] = make_float2(aR[ii][ff], aI[ii][ff]);
}

// ---------------- reduce partials + edges + mixing + irfft weighting ----------------
__global__ void mix_kernel(const float* __restrict__ xnext, int m, int nchunk, int lev) {
    int f = blockIdx.x;
    int b = blockIdx.y;
    int tid = threadIdx.x;          // 32 threads
    __shared__ float Dre[16], Dim[16], Xre[16], Xim[16];
    int arr = tid >> 4, i = tid & 15;
    const float2* P = (const float2*)g_part;
    float sre = 0.f, sim = 0.f;
    size_t base = (((size_t)arr * BB + b) * nchunk) * 64 + f;
    for (int ch = 0; ch < nchunk; ch++) {
        float2 p = P[(base + (size_t)ch * 64) * 16 + i];
        sre += p.x; sim += p.y;
    }
    // edge samples t=0 and t=m/2: Re_f += e0 + (-1)^f e1
    float par = (f & 1) ? -1.f : 1.f;
    if (arr == 0) {
        sre += g_edge[b * 32 + i] + par * g_edge[b * 32 + 16 + i];
    } else {
        sre += xnext[(size_t)b * m * 16 + i]
             + par * xnext[((size_t)b * m + m / 2) * 16 + i];
    }
    if (arr == 0) { Dre[i] = sre; Dim[i] = sim; }
    else          { Xre[i] = sre; Xim[i] = sim; }
    __syncthreads();
    float r = 0.f, q = 0.f;
    if (arr == 0) {
#pragma unroll
        for (int ii = 0; ii < 16; ii++) {
            float ar = g_wT[0 * 16384 + f * 256 + ii * 16 + i];
            float ai = g_wT[1 * 16384 + f * 256 + ii * 16 + i];
            r += Dre[ii] * ar - Dim[ii] * ai;
            q += Dre[ii] * ai + Dim[ii] * ar;
            float br = g_wT[2 * 16384 + f * 256 + ii * 16 + i];
            float bi = g_wT[3 * 16384 + f * 256 + ii * 16 + i];
            r += Xre[ii] * br - Xim[ii] * bi;
            q += Xre[ii] * bi + Xim[ii] * br;
        }
    } else {
#pragma unroll
        for (int ii = 0; ii < 16; ii++) {
            float cr = g_wT[4 * 16384 + f * 256 + ii * 16 + i];
            float ci = g_wT[5 * 16384 + f * 256 + ii * 16 + i];
            r += Dre[ii] * cr - Dim[ii] * ci;
            q += Dre[ii] * ci + Dim[ii] * cr;
        }
    }
    float wf = (f == 0) ? (1.0f / (float)m) : (2.0f / (float)m);
    size_t o = (size_t)lev * BB * 4096 + (((size_t)b * 2 + arr) * 128 + 2 * f) * 16 + i;
    g_spec[o]      = r * wf;
    g_spec[o + 16] = -q * wf;
}

// ---------------- Nyquist sample y[m/2] for all 6 shallow levels ----------------
__global__ void nyq_kernel(float* __restrict__ pUd, float* __restrict__ pUs) {
    const int ms[6]   = {8192, 4096, 2048, 1024, 512, 256};
    const int offs[6] = {0, 8192, 12288, 14336, 15360, 15872};
    int lev = blockIdx.x, b = blockIdx.y;
    int tid = threadIdx.x;           // 32 = 16 j x 2 arr
    int arr = tid >> 4, j = tid & 15;
    int m = ms[lev];
    const float* sp = g_spec + (size_t)lev * BB * 4096 + ((size_t)b * 2 + arr) * 2048;
    float acc = 0.f;
#pragma unroll
    for (int f = 0; f < 64; f += 2) acc += sp[32 * f + j];
#pragma unroll
    for (int f = 1; f < 64; f += 2) acc -= sp[32 * f + j];
    float* out = (arr ? pUs : pUd) + (size_t)BB * CKD * offs[lev];
    out[((size_t)b * m + m / 2) * 16 + j] = acc;
}

// =================================================================
// inv2: inverse truncated DFT with conjugate symmetry.
// =================================================================
__global__ void __launch_bounds__(128, 3) inv2_kernel(float* __restrict__ outUd,
                                                      float* __restrict__ outUs,
                                                      int m, int stride, int lev) {
    extern __shared__ float sm[];
    float* sB = sm;              // 128 k x 128 col = 16384
    float* sA = sB + 16384;      // 2 buf x (32 rows x 32 t) = 2048
    int tid = threadIdx.x;
    int t0 = blockIdx.x * 32;
    int b0 = blockIdx.y * 4;

    const float4* spec4 = (const float4*)g_spec + (size_t)lev * BB * 1024;
    float4* sB4 = (float4*)sB;
    for (int id = tid; id < 4096; id += 128) {
        int k = id >> 5, col4 = id & 31;
        int bl = col4 >> 3, arr = (col4 >> 2) & 1, j4 = col4 & 3;
        sB4[id] = spec4[(((size_t)(b0 + bl) * 2 + arr) * 128 + k) * 4 + j4];
    }
    const float2* T2 = (const float2*)g_tabT;
    int tl = tid & 31;
    int fq = tid >> 5;
    auto stageA = [&](int st, int buf) {
#pragma unroll
        for (int q = 0; q < 4; q++) {
            int fp = fq * 4 + q;
            int f = st * 16 + fp;
            float2 cs = T2[(size_t)f * 8192 + (size_t)(t0 + tl) * stride];
            sA[buf * 1024 + (2 * fp) * 32 + tl]     = cs.x;
            sA[buf * 1024 + (2 * fp + 1) * 32 + tl] = cs.y;
        }
    };
    stageA(0, 0);
    __syncthreads();

    int cg = tid & 15;
    int tg = tid >> 4;
    float u[4][8] = {}, v[4][8] = {};

    for (int st = 0; st < 4; st++) {
        int cur = st & 1;
        if (st < 3) stageA(st + 1, cur ^ 1);
        const float* A = &sA[cur * 1024];
        const float* Bst = &sB[st * 32 * 128];
#pragma unroll 4
        for (int fp = 0; fp < 16; fp++) {
            float4 ac = *(const float4*)&A[(2 * fp) * 32 + tg * 4];
            float4 as = *(const float4*)&A[(2 * fp + 1) * 32 + tg * 4];
            float4 bu0 = *(const float4*)&Bst[(2 * fp) * 128 + cg * 8];
            float4 bu1 = *(const float4*)&Bst[(2 * fp) * 128 + cg * 8 + 4];
            float4 bv0 = *(const float4*)&Bst[(2 * fp + 1) * 128 + cg * 8];
            float4 bv1 = *(const float4*)&Bst[(2 * fp + 1) * 128 + cg * 8 + 4];
            float acv[4] = {ac.x, ac.y, ac.z, ac.w};
            float asv[4] = {as.x, as.y, as.z, as.w};
            float buv[8] = {bu0.x, bu0.y, bu0.z, bu0.w, bu1.x, bu1.y, bu1.z, bu1.w};
            float bvv[8] = {bv0.x, bv0.y, bv0.z, bv0.w, bv1.x, bv1.y, bv1.z, bv1.w};
#pragma unroll
            for (int r = 0; r < 4; r++)
#pragma unroll
                for (int c = 0; c < 8; c++) {
                    u[r][c] += acv[r] * buv[c];
                    v[r][c] += asv[r] * bvv[c];
                }
        }
        __syncthreads();
    }
    int bl = cg >> 2, arr = (cg >> 1) & 1, j0 = (cg & 1) * 8;
    float* outp = (arr ? outUs : outUd) + ((size_t)(b0 + bl) * m) * 16 + j0;
#pragma unroll
    for (int r = 0; r < 4; r++) {
        int t = t0 + tg * 4 + r;
        float4 y0 = make_float4(u[r][0] + v[r][0], u[r][1] + v[r][1],
                                u[r][2] + v[r][2], u[r][3] + v[r][3]);
        float4 y1 = make_float4(u[r][4] + v[r][4], u[r][5] + v[r][5],
                                u[r][6] + v[r][6], u[r][7] + v[r][7]);
        *(float4*)&outp[(size_t)t * 16]     = y0;
        *(float4*)&outp[(size_t)t * 16 + 4] = y1;
        if (t > 0) {
            size_t tm = (size_t)(m - t);
            float4 z0 = make_float4(u[r][0] - v[r][0], u[r][1] - v[r][1],
                                    u[r][2] - v[r][2], u[r][3] - v[r][3]);
            float4 z1 = make_float4(u[r][4] - v[r][4], u[r][5] - v[r][5],
                                    u[r][6] - v[r][6], u[r][7] - v[r][7]);
            *(float4*)&outp[tm * 16]     = z0;
            *(float4*)&outp[tm * 16 + 4] = z1;
        }
    }
}

// =================================================================
// deep_kernel: levels 6..13 (m=128..1) entirely in smem.
// =================================================================
__global__ void __launch_bounds__(256, 1) deep_kernel(
        const float* __restrict__ xin, float* __restrict__ xout,
        const float* __restrict__ ecd, const float* __restrict__ ecs,
        const float* __restrict__ rce, const float* __restrict__ rco,
        const float* __restrict__ t0w, const float* __restrict__ t0b) {
    extern __shared__ float dsm[];
    float* X0 = dsm;
    float* X1 = X0 + 4096;
    float* D  = X1 + 4096;
    float* UD = D + 2048;
    float* US = UD + 4080;
    float* SP = US + 4080;
    float* MS = SP + 4096;
    __shared__ float fl[148];
    int b = blockIdx.x, tid = threadIdx.x;
    if (tid < 32)       fl[tid] = ecd[tid];
    else if (tid < 64)  fl[tid] = ecs[tid - 32];
    else if (tid < 96)  fl[tid] = rce[tid - 64];
    else if (tid < 128) fl[tid] = rco[tid - 96];
    else if (tid < 144) fl[tid] = t0w[tid - 128];
    else if (tid < 148) fl[tid] = t0b[tid - 144];
    for (int i = tid; i < 4096; i += 256) X0[i] = xin[(size_t)b * 4096 + i];
    __syncthreads();

    float* xc = X0; float* xn = X1;
    int loff[8];
    int off = 0;
    for (int li = 0; li < 8; li++) { loff[li] = off; off += 128 >> li; }

    for (int li = 0; li < 8; li++) {
        int m = 128 >> li;
        int stride = 8192 / m;
        for (int it = tid; it < m * 4; it += 256) {
            int c = it & 3, s = it >> 2;
            float xa[8];
#pragma unroll
            for (int p = 0; p < 4; p++) {
                xa[p]     = xc[(2 * s) * 16 + c * 4 + p];
                xa[p + 4] = xc[(2 * s + 1) * 16 + c * 4 + p];
            }
            float dv[4] = {0, 0, 0, 0}, sv[4] = {0, 0, 0, 0};
#pragma unroll
            for (int p = 0; p < 8; p++) {
                float xv = xa[p];
#pragma unroll
                for (int j = 0; j < 4; j++) {
                    dv[j] += xv * fl[p * 4 + j];
                    sv[j] += xv * fl[32 + p * 4 + j];
                }
            }
#pragma unroll
            for (int j = 0; j < 4; j++) {
                D[s * 16 + c * 4 + j]  = dv[j];
                xn[s * 16 + c * 4 + j] = sv[j];
            }
        }
        __syncthreads();
        int l = (m / 2 + 1 < 64) ? m / 2 + 1 : 64;
        for (int it = tid; it < 2 * l * 16; it += 256) {
            int i = it & 15;
            int f = (it >> 4) % l;
            int arr = it / (16 * l);
            const float* src = arr ? xn : D;
            float re = 0.f, im = 0.f;
            for (int t = 0; t < m; t++) {
                float v = src[t * 16 + i];
                re += v * g_tabc[(t * stride) * 64 + f];
                im -= v * g_tabs[(t * stride) * 64 + f];
            }
            SP[((arr * 64 + f) * 2 + 0) * 16 + i] = re;
            SP[((arr * 64 + f) * 2 + 1) * 16 + i] = im;
        }
        __syncthreads();
        for (int it = tid; it < 2 * l * 16; it += 256) {
            int o = it & 15;
            int f = (it >> 4) % l;
            int arr = it / (16 * l);
            float r = 0.f, q = 0.f;
            if (arr == 0) {
#pragma unroll 4
                for (int i2 = 0; i2 < 16; i2++) {
                    float Dr = SP[((0 * 64 + f) * 2 + 0) * 16 + i2];
                    float Di = SP[((0 * 64 + f) * 2 + 1) * 16 + i2];
                    float Xr = SP[((1 * 64 + f) * 2 + 0) * 16 + i2];
                    float Xi = SP[((1 * 64 + f) * 2 + 1) * 16 + i2];
                    float ar = g_wT[0 * 16384 + f * 256 + i2 * 16 + o];
                    float ai = g_wT[1 * 16384 + f * 256 + i2 * 16 + o];
                    float br = g_wT[2 * 16384 + f * 256 + i2 * 16 + o];
                    float bi = g_wT[3 * 16384 + f * 256 + i2 * 16 + o];
                    r += Dr * ar - Di * ai + Xr * br - Xi * bi;
                    q += Dr * ai + Di * ar + Xr * bi + Xi * br;
                }
            } else {
#pragma unroll 4
                for (int i2 = 0; i2 < 16; i2++) {
                    float Dr = SP[((0 * 64 + f) * 2 + 0) * 16 + i2];
                    float Di = SP[((0 * 64 + f) * 2 + 1) * 16 + i2];
                    float cr = g_wT[4 * 16384 + f * 256 + i2 * 16 + o];
                    float ci = g_wT[5 * 16384 + f * 256 + i2 * 16 + o];
                    r += Dr * cr - Di * ci;
                    q += Dr * ci + Di * cr;
                }
            }
            float wf = (f == 0 || 2 * f == m) ? (1.0f / (float)m) : (2.0f / (float)m);
            MS[((arr * 64 + f) * 2 + 0) * 16 + o] = r * wf;
            MS[((arr * 64 + f) * 2 + 1) * 16 + o] = q * wf;
        }
        __syncthreads();
        for (int it = tid; it < 2 * m * 16; it += 256) {
            int o = it & 15;
            int t = (it >> 4) % m;
            int arr = it / (16 * m);
            float acc = 0.f;
            for (int f = 0; f < l; f++) {
                float r = MS[((arr * 64 + f) * 2 + 0) * 16 + o];
                float q = MS[((arr * 64 + f) * 2 + 1) * 16 + o];
                acc += r * g_tabc[(t * stride) * 64 + f] - q * g_tabs[(t * stride) * 64 + f];
            }
            (arr ? US : UD)[(loff[li] + t) * 16 + o] = acc;
        }
        __syncthreads();
        float* tmp = xc; xc = xn; xn = tmp;
    }
    if (tid < 16) {
        int c = tid >> 2, o = tid & 3;
        float acc = fl[144 + o];
#pragma unroll
        for (int p = 0; p < 4; p++) acc += xc[c * 4 + p] * fl[128 + o * 4 + p];
        xn[tid] = acc;
    }
    __syncthreads();
    { float* tmp = xc; xc = xn; xn = tmp; }
    for (int li = 7; li >= 0; li--) {
        int m = 128 >> li;
        for (int it = tid; it < m * 4; it += 256) {
            int c = it & 3, s = it >> 2;
            float xs[4], ud[4];
#pragma unroll
            for (int j = 0; j < 4; j++) {
                xs[j] = xc[s * 16 + c * 4 + j] + US[(loff[li] + s) * 16 + c * 4 + j];
                ud[j] = UD[(loff[li] + s) * 16 + c * 4 + j];
            }
            float e[4] = {0, 0, 0, 0}, o4[4] = {0, 0, 0, 0};
#pragma unroll
            for (int p = 0; p < 4; p++)
#pragma unroll
                for (int j = 0; j < 4; j++) {
                    e[j]  += xs[p] * fl[64 + p * 4 + j] + ud[p] * fl[64 + (p + 4) * 4 + j];
                    o4[j] += xs[p] * fl[96 + p * 4 + j] + ud[p] * fl[96 + (p + 4) * 4 + j];
                }
#pragma unroll
            for (int j = 0; j < 4; j++) {
                xn[(2 * s) * 16 + c * 4 + j]     = e[j];
                xn[(2 * s + 1) * 16 + c * 4 + j] = o4[j];
            }
        }
        __syncthreads();
        float* tmp = xc; xc = xn; xn = tmp;
    }
    for (int i = tid; i < 4096; i += 256) xout[(size_t)b * 4096 + i] = xc[i];
}

// ---------------- reconstruction step (levels 0-5) ----------------
__global__ void recon_kernel(const float* __restrict__ xin, const float* __restrict__ Ud,
                             const float* __restrict__ Us, const float* __restrict__ rce,
                             const float* __restrict__ rco, float* __restrict__ out, int m) {
    __shared__ float se[32], so[32];
    int tid = threadIdx.x;
    if (tid < 32)      se[tid]      = rce[tid];
    else if (tid < 64) so[tid - 32] = rco[tid - 32];
    __syncthreads();
    int idx = blockIdx.x * blockDim.x + tid;
    if (idx >= BB * m * 4) return;
    int c = idx & 3;
    int s = (idx >> 2) % m;
    int b = idx / (m * 4);
    size_t r = ((size_t)b * m + s) * 16 + c * 4;
    float4 xv = *(const float4*)&xin[r];
    float4 uv = *(const float4*)&Us[r];
    float4 dv = *(const float4*)&Ud[r];
    float xs[4] = {xv.x + uv.x, xv.y + uv.y, xv.z + uv.z, xv.w + uv.w};
    float ud[4] = {dv.x, dv.y, dv.z, dv.w};
    float e[4] = {0, 0, 0, 0}, o[4] = {0, 0, 0, 0};
#pragma unroll
    for (int p = 0; p < 4; p++)
#pragma unroll
        for (int j = 0; j < 4; j++) {
            e[j] += xs[p] * se[p * 4 + j] + ud[p] * se[(p + 4) * 4 + j];
            o[j] += xs[p] * so[p * 4 + j] + ud[p] * so[(p + 4) * 4 + j];
        }
    size_t w = ((size_t)b * 2 * m + 2 * s) * 16 + c * 4;
    *(float4*)&out[w]      = make_float4(e[0], e[1], e[2], e[3]);
    *(float4*)&out[w + 16] = make_float4(o[0], o[1], o[2], o[3]);
}

// ---------------- host orchestration ----------------
extern "C" void kernel_launch(void* const* d_in, const int* in_sizes, int n_in,
                              void* d_out, int out_size) {
    const float* x_in = (const float*)d_in[0];
    const float* ec_s = (const float*)d_in[1];
    const float* ec_d = (const float*)d_in[2];
    const float* rc_e = (const float*)d_in[3];
    const float* rc_o = (const float*)d_in[4];
    const float* t0_w = (const float*)d_in[5];
    const float* t0_b = (const float*)d_in[6];

    const int DFWD_SM = 12288 * 4;
    const int INV_SM  = (16384 + 2048) * 4;
    const int DEEP_SM = (4096 + 4096 + 2048 + 4080 + 4080 + 4096 + 4096) * 4;
    cudaFuncSetAttribute(dfwd_kernel, cudaFuncAttributeMaxDynamicSharedMemorySize, DFWD_SM);
    cudaFuncSetAttribute(inv2_kernel, cudaFuncAttributeMaxDynamicSharedMemorySize, INV_SM);
    cudaFuncSetAttribute(deep_kernel, cudaFuncAttributeMaxDynamicSharedMemorySize, DEEP_SM);

    tab_row_kernel<<<2048, 256>>>();
    tab_T_kernel<<<2048, 256>>>();
    wprep_kernel<<<(6 * 16384 + 255) / 256, 256>>>(
        (const float*)d_in[7], (const float*)d_in[8], (const float*)d_in[9],
        (const float*)d_in[10], (const float*)d_in[11], (const float*)d_in[12]);

    float *px0, *px1, *pd, *pUd, *pUs;
    cudaGetSymbolAddress((void**)&px0, g_x0);
    cudaGetSymbolAddress((void**)&px1, g_x1);
    cudaGetSymbolAddress((void**)&pd,  g_d);
    cudaGetSymbolAddress((void**)&pUd, g_Ud);
    cudaGetSymbolAddress((void**)&pUs, g_Us);

    float* xb[2] = {px0, px1};
    size_t offs[6];
    size_t off = 0;
    const float* src = x_in;

    // levels 0..5: folded decompose+fwd, mix(+edges), symmetric inverse
    for (int lev = 0; lev < 6; lev++) {
        int m = NN >> (lev + 1);                 // 8192..256
        offs[lev] = off;
        int stride = MAXM / m;
        int half = m / 2;
        int nchunk = half / 128; if (nchunk < 1) nchunk = 1;   // clen = 128
        float* xnext = xb[lev & 1];

        dfwd_kernel<<<dim3(8, nchunk), 256, DFWD_SM>>>(src, xnext, ec_d, ec_s, m, stride, nchunk);
        mix_kernel<<<dim3(64, BB), 32>>>(xnext, m, nchunk, lev);
        inv2_kernel<<<dim3(m / 64, 8), 128, INV_SM>>>(
            pUd + (size_t)BB * CKD * off, pUs + (size_t)BB * CKD * off, m, stride, lev);

        off += m;
        src = xnext;
    }

    // Nyquist samples y[m/2] for all 6 levels
    nyq_kernel<<<dim3(6, BB), 32>>>(pUd, pUs);

    // levels 6..13 + T0 + their reconstruction, all in one kernel
    deep_kernel<<<BB, 256, DEEP_SM>>>(src, pd, ec_d, ec_s, rc_e, rc_o, t0_w, t0_b);

    // reconstruction levels 5..0
    const float* curx = pd;
    int flip = 0;
    for (int lev = 5; lev >= 0; lev--) {
        int m = NN >> (lev + 1);
        float* dst = (lev == 0) ? (float*)d_out : xb[flip];
        int total = BB * m * 4;
        recon_kernel<<<(total + 255) / 256, 256>>>(
            curx, pUd + (size_t)BB * CKD * offs[lev], pUs + (size_t)BB * CKD * offs[lev],
            rc_e, rc_o, dst, m);
        curx = dst;
        flip ^= 1;
    }
}

// round 7
// speedup vs baseline: 1.6647x; 1.3315x over previous
#include <cuda_runtime.h>

#define BB   32
#define NN   16384
#define CKD  16
#define MAXM 8192
#define TOTCH 156

// ---------------- device scratch (static, no allocations) ----------------
__device__ __align__(256) float g_x0 [BB*MAXM*CKD];
__device__ __align__(256) float g_x1 [BB*MAXM*CKD];
__device__ __align__(256) float g_d  [BB*MAXM*CKD];     // reused as deep-kernel output
__device__ __align__(256) float g_Ud [BB*(NN-1)*CKD];
__device__ __align__(256) float g_Us [BB*(NN-1)*CKD];
__device__ __align__(256) float g_part[2ull*BB*TOTCH*64*CKD*2];
__device__ __align__(256) float g_spec[6ull*BB*4096];   // [lev][b][arr][k=2f(re)/2f+1(-im)][j]
__device__ __align__(256) float g_edge[6*BB*64];        // [lev][b][d0|dmh|x0|xmh]
__device__ __align__(256) float g_tabc[MAXM*64];        // [t][f] cos
__device__ __align__(256) float g_tabs[MAXM*64];        // [t][f] sin
__device__ __align__(256) float g_tabT[64*MAXM*2];      // [f][t](cos,sin) interleaved
__device__ __align__(256) float g_wT  [6*64*16*16];     // [arr][f][i][o]

// ---------------- twiddle tables ----------------
__global__ void tab_row_kernel() {
    int idx = blockIdx.x * blockDim.x + threadIdx.x;   // t*64 + f
    int t = idx >> 6, f = idx & 63;
    float ph = (float)(f * t) * (2.0f / 8192.0f);
    float s, c; sincospif(ph, &s, &c);
    g_tabc[idx] = c;
    g_tabs[idx] = s;
}
__global__ void tab_T_kernel() {
    int idx = blockIdx.x * blockDim.x + threadIdx.x;   // f*8192 + t
    int f = idx >> 13, t = idx & 8191;
    float ph = (float)(f * t) * (2.0f / 8192.0f);
    float s, c; sincospif(ph, &s, &c);
    g_tabT[2*idx + 0] = c;
    g_tabT[2*idx + 1] = s;
}

// ---------------- weight transpose: [i][o][f] -> [arr][f][i][o] ----------------
__global__ void wprep_kernel(const float* __restrict__ a0, const float* __restrict__ a1,
                             const float* __restrict__ a2, const float* __restrict__ a3,
                             const float* __restrict__ a4, const float* __restrict__ a5) {
    int idx = blockIdx.x * blockDim.x + threadIdx.x;
    if (idx >= 6*16384) return;
    int arr = idx >> 14;
    int r   = idx & 16383;
    int f = r >> 8, i = (r >> 4) & 15, o = r & 15;
    const float* src = (arr == 0) ? a0 : (arr == 1) ? a1 : (arr == 2) ? a2 :
                       (arr == 3) ? a3 : (arr == 4) ? a4 : a5;
    g_wT[idx] = src[(i * 16 + o) * 64 + f];
}

// =================================================================
// dfwd: fused decompose + FOLDED forward truncated DFT.
// p = d_s + d_{m-s}, q = d_s - d_{m-s}; Re=sum p cos, Im=-sum q sin.
// s=0 & m/2 rows (d and x) go to per-level g_edge.
// =================================================================
__global__ void __launch_bounds__(256, 2) dfwd_kernel(
        const float* __restrict__ xin, float* __restrict__ xnext,
        const float* __restrict__ ecd, const float* __restrict__ ecs,
        int m, int stride, int nchunk, int choff, int lev) {
    extern __shared__ float sm[];
    float* s_dp = sm;            // 2048
    float* s_dq = s_dp + 2048;
    float* s_xp = s_dq + 2048;
    float* s_xq = s_xp + 2048;
    float* s_tc = s_xq + 2048;
    float* s_ts = s_tc + 2048;   // total 12288 floats
    __shared__ float fl[64];
    int tid = threadIdx.x;
    int b0 = blockIdx.x * 4;
    int ch = blockIdx.y;
    int clen = (m / 2) / nchunk;      // multiple of 32
    int T0base = ch * clen;
    if (tid < 64) fl[tid] = (tid < 32) ? ecd[tid] : ecs[tid - 32];
    __syncthreads();   // fl visible before decompose reads it

    int bloc = tid >> 6;
    int sub  = tid & 63;
    int arr  = sub >> 5;
    int lane32 = sub & 31;
    int i0 = (lane32 & 1) * 8;
    int f0 = (lane32 >> 1) * 4;
    float aR[8][4] = {}, aI[8][4] = {};

    for (int tb = 0; tb < clen; tb += 32) {
        int T0 = T0base + tb;
        {
            float4* tc4 = (float4*)s_tc;
            float4* ts4 = (float4*)s_ts;
            for (int id = tid; id < 512; id += 256) {
                int t = id >> 4, q = id & 15;
                size_t g = ((size_t)(T0 + t) * stride) * 16 + q;
                tc4[id] = ((const float4*)g_tabc)[g];
                ts4[id] = ((const float4*)g_tabs)[g];
            }
        }
        for (int id = tid; id < 512; id += 256) {
            int c = id & 3, t = (id >> 2) & 31, bl = id >> 7;
            int s = T0 + t;
            int smir = (s == 0) ? (m >> 1) : (m - s);
            size_t brow = (size_t)(b0 + bl) * (2 * m);
            float4 F0 = *(const float4*)&xin[(brow + 2 * s) * 16 + c * 4];
            float4 F1 = *(const float4*)&xin[(brow + 2 * s + 1) * 16 + c * 4];
            float4 M0 = *(const float4*)&xin[(brow + 2 * smir) * 16 + c * 4];
            float4 M1 = *(const float4*)&xin[(brow + 2 * smir + 1) * 16 + c * 4];
            float xf[8] = {F0.x, F0.y, F0.z, F0.w, F1.x, F1.y, F1.z, F1.w};
            float xm[8] = {M0.x, M0.y, M0.z, M0.w, M1.x, M1.y, M1.z, M1.w};
            float df[4] = {0,0,0,0}, sf[4] = {0,0,0,0};
            float dm[4] = {0,0,0,0}, smv[4] = {0,0,0,0};
#pragma unroll
            for (int p = 0; p < 8; p++) {
                float a = xf[p], bvv = xm[p];
#pragma unroll
                for (int j = 0; j < 4; j++) {
                    df[j]  += a * fl[p * 4 + j];
                    sf[j]  += a * fl[32 + p * 4 + j];
                    dm[j]  += bvv * fl[p * 4 + j];
                    smv[j] += bvv * fl[32 + p * 4 + j];
                }
            }
            size_t bnext = (size_t)(b0 + bl) * m;
            *(float4*)&xnext[(bnext + s) * 16 + c * 4]    = make_float4(sf[0], sf[1], sf[2], sf[3]);
            *(float4*)&xnext[(bnext + smir) * 16 + c * 4] = make_float4(smv[0], smv[1], smv[2], smv[3]);
            float pd[4], qd[4], px[4], qx[4];
            if (s == 0) {
                float* E = &g_edge[(lev * BB + (b0 + bl)) * 64];
                *(float4*)&E[c * 4]      = make_float4(df[0], df[1], df[2], df[3]);
                *(float4*)&E[16 + c * 4] = make_float4(dm[0], dm[1], dm[2], dm[3]);
                *(float4*)&E[32 + c * 4] = make_float4(sf[0], sf[1], sf[2], sf[3]);
                *(float4*)&E[48 + c * 4] = make_float4(smv[0], smv[1], smv[2], smv[3]);
#pragma unroll
                for (int j = 0; j < 4; j++) { pd[j]=0.f; qd[j]=0.f; px[j]=0.f; qx[j]=0.f; }
            } else {
#pragma unroll
                for (int j = 0; j < 4; j++) {
                    pd[j] = df[j] + dm[j];  qd[j] = df[j] - dm[j];
                    px[j] = sf[j] + smv[j]; qx[j] = sf[j] - smv[j];
                }
            }
            int soff = (bl * 32 + t) * 16 + c * 4;
            *(float4*)&s_dp[soff] = make_float4(pd[0], pd[1], pd[2], pd[3]);
            *(float4*)&s_dq[soff] = make_float4(qd[0], qd[1], qd[2], qd[3]);
            *(float4*)&s_xp[soff] = make_float4(px[0], px[1], px[2], px[3]);
            *(float4*)&s_xq[soff] = make_float4(qx[0], qx[1], qx[2], qx[3]);
        }
        __syncthreads();
        const float* sp = arr ? s_xp : s_dp;
        const float* sq = arr ? s_xq : s_dq;
#pragma unroll 4
        for (int tt = 0; tt < 32; tt++) {
            int base = (bloc * 32 + tt) * 16;
            float4 p0 = *(const float4*)&sp[base + i0];
            float4 p1 = *(const float4*)&sp[base + i0 + 4];
            float4 q0 = *(const float4*)&sq[base + i0];
            float4 q1 = *(const float4*)&sq[base + i0 + 4];
            float4 cv = *(const float4*)&s_tc[tt * 64 + f0];
            float4 sv = *(const float4*)&s_ts[tt * 64 + f0];
            float pp[8] = {p0.x, p0.y, p0.z, p0.w, p1.x, p1.y, p1.z, p1.w};
            float qq[8] = {q0.x, q0.y, q0.z, q0.w, q1.x, q1.y, q1.z, q1.w};
            float cf[4] = {cv.x, cv.y, cv.z, cv.w};
            float sff[4] = {sv.x, sv.y, sv.z, sv.w};
#pragma unroll
            for (int ii = 0; ii < 8; ii++)
#pragma unroll
                for (int ff = 0; ff < 4; ff++) {
                    aR[ii][ff] += pp[ii] * cf[ff];
                    aI[ii][ff] -= qq[ii] * sff[ff];
                }
        }
        __syncthreads();
    }
    float2* P = (float2*)g_part;
    int b = b0 + bloc;
    size_t base = (((size_t)arr * BB + b) * TOTCH + choff + ch) * 64;
#pragma unroll
    for (int ff = 0; ff < 4; ff++)
#pragma unroll
        for (int ii = 0; ii < 8; ii++)
            P[(base + f0 + ff) * 16 + i0 + ii] = make_float2(aR[ii][ff], aI[ii][ff]);
}

// ---------------- merged mix: all 6 levels in one launch ----------------
__global__ void mix_kernel() {
    const int nch[6] = {64, 32, 32, 16, 8, 4};
    const int cho[6] = {0, 64, 96, 128, 144, 152};
    int f = blockIdx.x;
    int b = blockIdx.y;
    int lev = blockIdx.z;
    int m = 16384 >> (lev + 1);
    int tid = threadIdx.x;          // 32 threads
    __shared__ float Dre[16], Dim[16], Xre[16], Xim[16];
    int arr = tid >> 4, i = tid & 15;
    const float2* P = (const float2*)g_part;
    float sre = 0.f, sim = 0.f;
    size_t base = (((size_t)arr * BB + b) * TOTCH + cho[lev]) * 64 + f;
    int nc = nch[lev];
    for (int ch = 0; ch < nc; ch++) {
        float2 p = P[(base + (size_t)ch * 64) * 16 + i];
        sre += p.x; sim += p.y;
    }
    // edge samples t=0 and t=m/2: Re_f += e0 + (-1)^f e1
    float par = (f & 1) ? -1.f : 1.f;
    const float* E = &g_edge[(lev * BB + b) * 64];
    sre += E[(arr ? 32 : 0) + i] + par * E[(arr ? 48 : 16) + i];
    if (arr == 0) { Dre[i] = sre; Dim[i] = sim; }
    else          { Xre[i] = sre; Xim[i] = sim; }
    __syncthreads();
    float r = 0.f, q = 0.f;
    if (arr == 0) {
#pragma unroll
        for (int ii = 0; ii < 16; ii++) {
            float ar = g_wT[0 * 16384 + f * 256 + ii * 16 + i];
            float ai = g_wT[1 * 16384 + f * 256 + ii * 16 + i];
            r += Dre[ii] * ar - Dim[ii] * ai;
            q += Dre[ii] * ai + Dim[ii] * ar;
            float br = g_wT[2 * 16384 + f * 256 + ii * 16 + i];
            float bi = g_wT[3 * 16384 + f * 256 + ii * 16 + i];
            r += Xre[ii] * br - Xim[ii] * bi;
            q += Xre[ii] * bi + Xim[ii] * br;
        }
    } else {
#pragma unroll
        for (int ii = 0; ii < 16; ii++) {
            float cr = g_wT[4 * 16384 + f * 256 + ii * 16 + i];
            float ci = g_wT[5 * 16384 + f * 256 + ii * 16 + i];
            r += Dre[ii] * cr - Dim[ii] * ci;
            q += Dre[ii] * ci + Dim[ii] * cr;
        }
    }
    float wf = (f == 0) ? (1.0f / (float)m) : (2.0f / (float)m);
    size_t o = (size_t)lev * BB * 4096 + (((size_t)b * 2 + arr) * 128 + 2 * f) * 16 + i;
    g_spec[o]      = r * wf;
    g_spec[o + 16] = -q * wf;
}

// ---------------- Nyquist sample y[m/2] for all 6 shallow levels ----------------
__global__ void nyq_kernel(float* __restrict__ pUd, float* __restrict__ pUs) {
    const int ms[6]   = {8192, 4096, 2048, 1024, 512, 256};
    const int offs[6] = {0, 8192, 12288, 14336, 15360, 15872};
    int lev = blockIdx.x, b = blockIdx.y;
    int tid = threadIdx.x;           // 32 = 16 j x 2 arr
    int arr = tid >> 4, j = tid & 15;
    int m = ms[lev];
    const float* sp = g_spec + (size_t)lev * BB * 4096 + ((size_t)b * 2 + arr) * 2048;
    float acc = 0.f;
#pragma unroll
    for (int f = 0; f < 64; f += 2) acc += sp[32 * f + j];
#pragma unroll
    for (int f = 1; f < 64; f += 2) acc -= sp[32 * f + j];
    float* out = (arr ? pUs : pUd) + (size_t)BB * CKD * offs[lev];
    out[((size_t)b * m + m / 2) * 16 + j] = acc;
}

// =================================================================
// inv2: inverse truncated DFT with conjugate symmetry, ALL levels
// in one launch. grid (252 tiles, 8 b-groups).
// =================================================================
__global__ void __launch_bounds__(128, 3) inv2_kernel(float* __restrict__ pUd,
                                                      float* __restrict__ pUs) {
    const int tstart[6] = {0, 128, 192, 224, 240, 248};
    const int offs[6]   = {0, 8192, 12288, 14336, 15360, 15872};
    extern __shared__ float sm[];
    float* sB = sm;              // 128 k x 128 col = 16384
    float* sA = sB + 16384;      // 2 buf x (32 rows x 32 t) = 2048
    int tid = threadIdx.x;
    int bx = blockIdx.x;
    int lev;
    if (bx < 128) lev = 0; else if (bx < 192) lev = 1; else if (bx < 224) lev = 2;
    else if (bx < 240) lev = 3; else if (bx < 248) lev = 4; else lev = 5;
    int m = 16384 >> (lev + 1);
    int stride = 1 << lev;
    int t0 = (bx - tstart[lev]) * 32;
    int b0 = blockIdx.y * 4;
    float* outUd = pUd + (size_t)BB * CKD * offs[lev];
    float* outUs = pUs + (size_t)BB * CKD * offs[lev];

    const float4* spec4 = (const float4*)g_spec + (size_t)lev * BB * 1024;
    float4* sB4 = (float4*)sB;
    for (int id = tid; id < 4096; id += 128) {
        int k = id >> 5, col4 = id & 31;
        int bl = col4 >> 3, arr = (col4 >> 2) & 1, j4 = col4 & 3;
        sB4[id] = spec4[(((size_t)(b0 + bl) * 2 + arr) * 128 + k) * 4 + j4];
    }
    const float2* T2 = (const float2*)g_tabT;
    int tl = tid & 31;
    int fq = tid >> 5;
    auto stageA = [&](int st, int buf) {
#pragma unroll
        for (int q = 0; q < 4; q++) {
            int fp = fq * 4 + q;
            int f = st * 16 + fp;
            float2 cs = T2[(size_t)f * 8192 + (size_t)(t0 + tl) * stride];
            sA[buf * 1024 + (2 * fp) * 32 + tl]     = cs.x;
            sA[buf * 1024 + (2 * fp + 1) * 32 + tl] = cs.y;
        }
    };
    stageA(0, 0);
    __syncthreads();

    int cg = tid & 15;
    int tg = tid >> 4;
    float u[4][8] = {}, v[4][8] = {};

    for (int st = 0; st < 4; st++) {
        int cur = st & 1;
        if (st < 3) stageA(st + 1, cur ^ 1);
        const float* A = &sA[cur * 1024];
        const float* Bst = &sB[st * 32 * 128];
#pragma unroll 4
        for (int fp = 0; fp < 16; fp++) {
            float4 ac = *(const float4*)&A[(2 * fp) * 32 + tg * 4];
            float4 as = *(const float4*)&A[(2 * fp + 1) * 32 + tg * 4];
            float4 bu0 = *(const float4*)&Bst[(2 * fp) * 128 + cg * 8];
            float4 bu1 = *(const float4*)&Bst[(2 * fp) * 128 + cg * 8 + 4];
            float4 bv0 = *(const float4*)&Bst[(2 * fp + 1) * 128 + cg * 8];
            float4 bv1 = *(const float4*)&Bst[(2 * fp + 1) * 128 + cg * 8 + 4];
            float acv[4] = {ac.x, ac.y, ac.z, ac.w};
            float asv[4] = {as.x, as.y, as.z, as.w};
            float buv[8] = {bu0.x, bu0.y, bu0.z, bu0.w, bu1.x, bu1.y, bu1.z, bu1.w};
            float bvv[8] = {bv0.x, bv0.y, bv0.z, bv0.w, bv1.x, bv1.y, bv1.z, bv1.w};
#pragma unroll
            for (int r = 0; r < 4; r++)
#pragma unroll
                for (int c = 0; c < 8; c++) {
                    u[r][c] += acv[r] * buv[c];
                    v[r][c] += asv[r] * bvv[c];
                }
        }
        __syncthreads();
    }
    int bl = cg >> 2, arr = (cg >> 1) & 1, j0 = (cg & 1) * 8;
    float* outp = (arr ? outUs : outUd) + ((size_t)(b0 + bl) * m) * 16 + j0;
#pragma unroll
    for (int r = 0; r < 4; r++) {
        int t = t0 + tg * 4 + r;
        float4 y0 = make_float4(u[r][0] + v[r][0], u[r][1] + v[r][1],
                                u[r][2] + v[r][2], u[r][3] + v[r][3]);
        float4 y1 = make_float4(u[r][4] + v[r][4], u[r][5] + v[r][5],
                                u[r][6] + v[r][6], u[r][7] + v[r][7]);
        *(float4*)&outp[(size_t)t * 16]     = y0;
        *(float4*)&outp[(size_t)t * 16 + 4] = y1;
        if (t > 0) {
            size_t tm = (size_t)(m - t);
            float4 z0 = make_float4(u[r][0] - v[r][0], u[r][1] - v[r][1],
                                    u[r][2] - v[r][2], u[r][3] - v[r][3]);
            float4 z1 = make_float4(u[r][4] - v[r][4], u[r][5] - v[r][5],
                                    u[r][6] - v[r][6], u[r][7] - v[r][7]);
            *(float4*)&outp[tm * 16]     = z0;
            *(float4*)&outp[tm * 16 + 4] = z1;
        }
    }
}

// =================================================================
// deep_kernel: levels 6..13 (m=128..1) entirely in smem.
// =================================================================
__global__ void __launch_bounds__(256, 1) deep_kernel(
        const float* __restrict__ xin, float* __restrict__ xout,
        const float* __restrict__ ecd, const float* __restrict__ ecs,
        const float* __restrict__ rce, const float* __restrict__ rco,
        const float* __restrict__ t0w, const float* __restrict__ t0b) {
    extern __shared__ float dsm[];
    float* X0 = dsm;
    float* X1 = X0 + 4096;
    float* D  = X1 + 4096;
    float* UD = D + 2048;
    float* US = UD + 4080;
    float* SP = US + 4080;
    float* MS = SP + 4096;
    __shared__ float fl[148];
    int b = blockIdx.x, tid = threadIdx.x;
    if (tid < 32)       fl[tid] = ecd[tid];
    else if (tid < 64)  fl[tid] = ecs[tid - 32];
    else if (tid < 96)  fl[tid] = rce[tid - 64];
    else if (tid < 128) fl[tid] = rco[tid - 96];
    else if (tid < 144) fl[tid] = t0w[tid - 128];
    else if (tid < 148) fl[tid] = t0b[tid - 144];
    for (int i = tid; i < 4096; i += 256) X0[i] = xin[(size_t)b * 4096 + i];
    __syncthreads();

    float* xc = X0; float* xn = X1;
    int loff[8];
    int off = 0;
    for (int li = 0; li < 8; li++) { loff[li] = off; off += 128 >> li; }

    for (int li = 0; li < 8; li++) {
        int m = 128 >> li;
        int stride = 8192 / m;
        for (int it = tid; it < m * 4; it += 256) {
            int c = it & 3, s = it >> 2;
            float xa[8];
#pragma unroll
            for (int p = 0; p < 4; p++) {
                xa[p]     = xc[(2 * s) * 16 + c * 4 + p];
                xa[p + 4] = xc[(2 * s + 1) * 16 + c * 4 + p];
            }
            float dv[4] = {0, 0, 0, 0}, sv[4] = {0, 0, 0, 0};
#pragma unroll
            for (int p = 0; p < 8; p++) {
                float xv = xa[p];
#pragma unroll
                for (int j = 0; j < 4; j++) {
                    dv[j] += xv * fl[p * 4 + j];
                    sv[j] += xv * fl[32 + p * 4 + j];
                }
            }
#pragma unroll
            for (int j = 0; j < 4; j++) {
                D[s * 16 + c * 4 + j]  = dv[j];
                xn[s * 16 + c * 4 + j] = sv[j];
            }
        }
        __syncthreads();
        int l = (m / 2 + 1 < 64) ? m / 2 + 1 : 64;
        for (int it = tid; it < 2 * l * 16; it += 256) {
            int i = it & 15;
            int f = (it >> 4) % l;
            int arr = it / (16 * l);
            const float* src = arr ? xn : D;
            float re = 0.f, im = 0.f;
            for (int t = 0; t < m; t++) {
                float v = src[t * 16 + i];
                re += v * g_tabc[(t * stride) * 64 + f];
                im -= v * g_tabs[(t * stride) * 64 + f];
            }
            SP[((arr * 64 + f) * 2 + 0) * 16 + i] = re;
            SP[((arr * 64 + f) * 2 + 1) * 16 + i] = im;
        }
        __syncthreads();
        for (int it = tid; it < 2 * l * 16; it += 256) {
            int o = it & 15;
            int f = (it >> 4) % l;
            int arr = it / (16 * l);
            float r = 0.f, q = 0.f;
            if (arr == 0) {
#pragma unroll 4
                for (int i2 = 0; i2 < 16; i2++) {
                    float Dr = SP[((0 * 64 + f) * 2 + 0) * 16 + i2];
                    float Di = SP[((0 * 64 + f) * 2 + 1) * 16 + i2];
                    float Xr = SP[((1 * 64 + f) * 2 + 0) * 16 + i2];
                    float Xi = SP[((1 * 64 + f) * 2 + 1) * 16 + i2];
                    float ar = g_wT[0 * 16384 + f * 256 + i2 * 16 + o];
                    float ai = g_wT[1 * 16384 + f * 256 + i2 * 16 + o];
                    float br = g_wT[2 * 16384 + f * 256 + i2 * 16 + o];
                    float bi = g_wT[3 * 16384 + f * 256 + i2 * 16 + o];
                    r += Dr * ar - Di * ai + Xr * br - Xi * bi;
                    q += Dr * ai + Di * ar + Xr * bi + Xi * br;
                }
            } else {
#pragma unroll 4
                for (int i2 = 0; i2 < 16; i2++) {
                    float Dr = SP[((0 * 64 + f) * 2 + 0) * 16 + i2];
                    float Di = SP[((0 * 64 + f) * 2 + 1) * 16 + i2];
                    float cr = g_wT[4 * 16384 + f * 256 + i2 * 16 + o];
                    float ci = g_wT[5 * 16384 + f * 256 + i2 * 16 + o];
                    r += Dr * cr - Di * ci;
                    q += Dr * ci + Di * cr;
                }
            }
            float wf = (f == 0 || 2 * f == m) ? (1.0f / (float)m) : (2.0f / (float)m);
            MS[((arr * 64 + f) * 2 + 0) * 16 + o] = r * wf;
            MS[((arr * 64 + f) * 2 + 1) * 16 + o] = q * wf;
        }
        __syncthreads();
        for (int it = tid; it < 2 * m * 16; it += 256) {
            int o = it & 15;
            int t = (it >> 4) % m;
            int arr = it / (16 * m);
            float acc = 0.f;
            for (int f = 0; f < l; f++) {
                float r = MS[((arr * 64 + f) * 2 + 0) * 16 + o];
                float q = MS[((arr * 64 + f) * 2 + 1) * 16 + o];
                acc += r * g_tabc[(t * stride) * 64 + f] - q * g_tabs[(t * stride) * 64 + f];
            }
            (arr ? US : UD)[(loff[li] + t) * 16 + o] = acc;
        }
        __syncthreads();
        float* tmp = xc; xc = xn; xn = tmp;
    }
    if (tid < 16) {
        int c = tid >> 2, o = tid & 3;
        float acc = fl[144 + o];
#pragma unroll
        for (int p = 0; p < 4; p++) acc += xc[c * 4 + p] * fl[128 + o * 4 + p];
        xn[tid] = acc;
    }
    __syncthreads();
    { float* tmp = xc; xc = xn; xn = tmp; }
    for (int li = 7; li >= 0; li--) {
        int m = 128 >> li;
        for (int it = tid; it < m * 4; it += 256) {
            int c = it & 3, s = it >> 2;
            float xs[4], ud[4];
#pragma unroll
            for (int j = 0; j < 4; j++) {
                xs[j] = xc[s * 16 + c * 4 + j] + US[(loff[li] + s) * 16 + c * 4 + j];
                ud[j] = UD[(loff[li] + s) * 16 + c * 4 + j];
            }
            float e[4] = {0, 0, 0, 0}, o4[4] = {0, 0, 0, 0};
#pragma unroll
            for (int p = 0; p < 4; p++)
#pragma unroll
                for (int j = 0; j < 4; j++) {
                    e[j]  += xs[p] * fl[64 + p * 4 + j] + ud[p] * fl[64 + (p + 4) * 4 + j];
                    o4[j] += xs[p] * fl[96 + p * 4 + j] + ud[p] * fl[96 + (p + 4) * 4 + j];
                }
#pragma unroll
            for (int j = 0; j < 4; j++) {
                xn[(2 * s) * 16 + c * 4 + j]     = e[j];
                xn[(2 * s + 1) * 16 + c * 4 + j] = o4[j];
            }
        }
        __syncthreads();
        float* tmp = xc; xc = xn; xn = tmp;
    }
    for (int i = tid; i < 4096; i += 256) xout[(size_t)b * 4096 + i] = xc[i];
}

// ---------------- reconstruction step (levels 0-5) ----------------
__global__ void recon_kernel(const float* __restrict__ xin, const float* __restrict__ Ud,
                             const float* __restrict__ Us, const float* __restrict__ rce,
                             const float* __restrict__ rco, float* __restrict__ out, int m) {
    __shared__ float se[32], so[32];
    int tid = threadIdx.x;
    if (tid < 32)      se[tid]      = rce[tid];
    else if (tid < 64) so[tid - 32] = rco[tid - 32];
    __syncthreads();
    int idx = blockIdx.x * blockDim.x + tid;
    if (idx >= BB * m * 4) return;
    int c = idx & 3;
    int s = (idx >> 2) % m;
    int b = idx / (m * 4);
    size_t r = ((size_t)b * m + s) * 16 + c * 4;
    float4 xv = *(const float4*)&xin[r];
    float4 uv = *(const float4*)&Us[r];
    float4 dv = *(const float4*)&Ud[r];
    float xs[4] = {xv.x + uv.x, xv.y + uv.y, xv.z + uv.z, xv.w + uv.w};
    float ud[4] = {dv.x, dv.y, dv.z, dv.w};
    float e[4] = {0, 0, 0, 0}, o[4] = {0, 0, 0, 0};
#pragma unroll
    for (int p = 0; p < 4; p++)
#pragma unroll
        for (int j = 0; j < 4; j++) {
            e[j] += xs[p] * se[p * 4 + j] + ud[p] * se[(p + 4) * 4 + j];
            o[j] += xs[p] * so[p * 4 + j] + ud[p] * so[(p + 4) * 4 + j];
        }
    size_t w = ((size_t)b * 2 * m + 2 * s) * 16 + c * 4;
    *(float4*)&out[w]      = make_float4(e[0], e[1], e[2], e[3]);
    *(float4*)&out[w + 16] = make_float4(o[0], o[1], o[2], o[3]);
}

// ---------------- host orchestration ----------------
extern "C" void kernel_launch(void* const* d_in, const int* in_sizes, int n_in,
                              void* d_out, int out_size) {
    const float* x_in = (const float*)d_in[0];
    const float* ec_s = (const float*)d_in[1];
    const float* ec_d = (const float*)d_in[2];
    const float* rc_e = (const float*)d_in[3];
    const float* rc_o = (const float*)d_in[4];
    const float* t0_w = (const float*)d_in[5];
    const float* t0_b = (const float*)d_in[6];

    const int DFWD_SM = 12288 * 4;
    const int INV_SM  = (16384 + 2048) * 4;
    const int DEEP_SM = (4096 + 4096 + 2048 + 4080 + 4080 + 4096 + 4096) * 4;
    cudaFuncSetAttribute(dfwd_kernel, cudaFuncAttributeMaxDynamicSharedMemorySize, DFWD_SM);
    cudaFuncSetAttribute(inv2_kernel, cudaFuncAttributeMaxDynamicSharedMemorySize, INV_SM);
    cudaFuncSetAttribute(deep_kernel, cudaFuncAttributeMaxDynamicSharedMemorySize, DEEP_SM);

    tab_row_kernel<<<2048, 256>>>();
    tab_T_kernel<<<2048, 256>>>();
    wprep_kernel<<<(6 * 16384 + 255) / 256, 256>>>(
        (const float*)d_in[7], (const float*)d_in[8], (const float*)d_in[9],
        (const float*)d_in[10], (const float*)d_in[11], (const float*)d_in[12]);

    float *px0, *px1, *pd, *pUd, *pUs;
    cudaGetSymbolAddress((void**)&px0, g_x0);
    cudaGetSymbolAddress((void**)&px1, g_x1);
    cudaGetSymbolAddress((void**)&pd,  g_d);
    cudaGetSymbolAddress((void**)&pUd, g_Ud);
    cudaGetSymbolAddress((void**)&pUs, g_Us);

    float* xb[2] = {px0, px1};
    const int nchunks[6] = {64, 32, 32, 16, 8, 4};
    const int choffs[6]  = {0, 64, 96, 128, 144, 152};
    size_t offs[6];
    size_t off = 0;
    const float* src = x_in;

    // decomposition chain, levels 0..5
    for (int lev = 0; lev < 6; lev++) {
        int m = NN >> (lev + 1);                 // 8192..256
        offs[lev] = off;
        int stride = MAXM / m;
        float* xnext = xb[lev & 1];
        dfwd_kernel<<<dim3(8, nchunks[lev]), 256, DFWD_SM>>>(
            src, xnext, ec_d, ec_s, m, stride, nchunks[lev], choffs[lev], lev);
        off += m;
        src = xnext;
    }

    // all levels: mix, nyquist, inverse DFT (single launches)
    mix_kernel<<<dim3(64, BB, 6), 32>>>();
    nyq_kernel<<<dim3(6, BB), 32>>>(pUd, pUs);
    inv2_kernel<<<dim3(252, 8), 128, INV_SM>>>(pUd, pUs);

    // levels 6..13 + T0 + their reconstruction, all in one kernel
    deep_kernel<<<BB, 256, DEEP_SM>>>(src, pd, ec_d, ec_s, rc_e, rc_o, t0_w, t0_b);

    // reconstruction levels 5..0
    const float* curx = pd;
    int flip = 0;
    for (int lev = 5; lev >= 0; lev--) {
        int m = NN >> (lev + 1);
        float* dst = (lev == 0) ? (float*)d_out : xb[flip];
        int total = BB * m * 4;
        recon_kernel<<<(total + 255) / 256, 256>>>(
            curx, pUd + (size_t)BB * CKD * offs[lev], pUs + (size_t)BB * CKD * offs[lev],
            rc_e, rc_o, dst, m);
        curx = dst;
        flip ^= 1;
    }
}

// round 8
// speedup vs baseline: 2.0749x; 1.2464x over previous
#include <cuda_runtime.h>

#define BB   32
#define NN   16384
#define CKD  16
#define MAXM 8192
#define TOTCH 156

// ---------------- device scratch (static, no allocations) ----------------
__device__ __align__(256) float g_x0 [BB*MAXM*CKD];
__device__ __align__(256) float g_x1 [BB*MAXM*CKD];
__device__ __align__(256) float g_d  [BB*MAXM*CKD];     // deep-kernel output
__device__ __align__(256) float g_Ud [BB*(NN-1)*CKD];
__device__ __align__(256) float g_Us [BB*(NN-1)*CKD];
__device__ __align__(256) float g_part[2ull*BB*TOTCH*64*CKD*2];
__device__ __align__(256) float g_spec[6ull*BB*4096];   // [lev][b][arr][k=2f(re)/2f+1(-im)][j]
__device__ __align__(256) float g_edge[6*BB*64];        // [lev][b][d0|dmh|x0|xmh]
__device__ __align__(256) float g_tabc[MAXM*64];        // [t][f] cos
__device__ __align__(256) float g_tabs[MAXM*64];        // [t][f] sin
__device__ __align__(256) float g_tabT[64*MAXM*2];      // [f][t](cos,sin) interleaved
__device__ __align__(256) float g_wT  [6*64*16*16];     // [arr][f][i][o]

// ---------------- twiddle tables ----------------
__global__ void tab_row_kernel() {
    int idx = blockIdx.x * blockDim.x + threadIdx.x;   // t*64 + f
    int t = idx >> 6, f = idx & 63;
    float ph = (float)(f * t) * (2.0f / 8192.0f);
    float s, c; sincospif(ph, &s, &c);
    g_tabc[idx] = c;
    g_tabs[idx] = s;
}
__global__ void tab_T_kernel() {
    int idx = blockIdx.x * blockDim.x + threadIdx.x;   // f*8192 + t
    int f = idx >> 13, t = idx & 8191;
    float ph = (float)(f * t) * (2.0f / 8192.0f);
    float s, c; sincospif(ph, &s, &c);
    g_tabT[2*idx + 0] = c;
    g_tabT[2*idx + 1] = s;
}

// ---------------- weight transpose: [i][o][f] -> [arr][f][i][o] ----------------
__global__ void wprep_kernel(const float* __restrict__ a0, const float* __restrict__ a1,
                             const float* __restrict__ a2, const float* __restrict__ a3,
                             const float* __restrict__ a4, const float* __restrict__ a5) {
    int idx = blockIdx.x * blockDim.x + threadIdx.x;
    if (idx >= 6*16384) return;
    int arr = idx >> 14;
    int r   = idx & 16383;
    int f = r >> 8, i = (r >> 4) & 15, o = r & 15;
    const float* src = (arr == 0) ? a0 : (arr == 1) ? a1 : (arr == 2) ? a2 :
                       (arr == 3) ? a3 : (arr == 4) ? a4 : a5;
    g_wT[idx] = src[(i * 16 + o) * 64 + f];
}

// =================================================================
// dfwd: fused decompose + FOLDED forward truncated DFT.
// =================================================================
__global__ void __launch_bounds__(256, 2) dfwd_kernel(
        const float* __restrict__ xin, float* __restrict__ xnext,
        const float* __restrict__ ecd, const float* __restrict__ ecs,
        int m, int stride, int nchunk, int choff, int lev) {
    extern __shared__ float sm[];
    float* s_dp = sm;
    float* s_dq = s_dp + 2048;
    float* s_xp = s_dq + 2048;
    float* s_xq = s_xp + 2048;
    float* s_tc = s_xq + 2048;
    float* s_ts = s_tc + 2048;
    __shared__ float fl[64];
    int tid = threadIdx.x;
    int b0 = blockIdx.x * 4;
    int ch = blockIdx.y;
    int clen = (m / 2) / nchunk;
    int T0base = ch * clen;
    if (tid < 64) fl[tid] = (tid < 32) ? ecd[tid] : ecs[tid - 32];
    __syncthreads();

    int bloc = tid >> 6;
    int sub  = tid & 63;
    int arr  = sub >> 5;
    int lane32 = sub & 31;
    int i0 = (lane32 & 1) * 8;
    int f0 = (lane32 >> 1) * 4;
    float aR[8][4] = {}, aI[8][4] = {};

    for (int tb = 0; tb < clen; tb += 32) {
        int T0 = T0base + tb;
        {
            float4* tc4 = (float4*)s_tc;
            float4* ts4 = (float4*)s_ts;
            for (int id = tid; id < 512; id += 256) {
                int t = id >> 4, q = id & 15;
                size_t g = ((size_t)(T0 + t) * stride) * 16 + q;
                tc4[id] = ((const float4*)g_tabc)[g];
                ts4[id] = ((const float4*)g_tabs)[g];
            }
        }
        for (int id = tid; id < 512; id += 256) {
            int c = id & 3, t = (id >> 2) & 31, bl = id >> 7;
            int s = T0 + t;
            int smir = (s == 0) ? (m >> 1) : (m - s);
            size_t brow = (size_t)(b0 + bl) * (2 * m);
            float4 F0 = *(const float4*)&xin[(brow + 2 * s) * 16 + c * 4];
            float4 F1 = *(const float4*)&xin[(brow + 2 * s + 1) * 16 + c * 4];
            float4 M0 = *(const float4*)&xin[(brow + 2 * smir) * 16 + c * 4];
            float4 M1 = *(const float4*)&xin[(brow + 2 * smir + 1) * 16 + c * 4];
            float xf[8] = {F0.x, F0.y, F0.z, F0.w, F1.x, F1.y, F1.z, F1.w};
            float xm[8] = {M0.x, M0.y, M0.z, M0.w, M1.x, M1.y, M1.z, M1.w};
            float df[4] = {0,0,0,0}, sf[4] = {0,0,0,0};
            float dm[4] = {0,0,0,0}, smv[4] = {0,0,0,0};
#pragma unroll
            for (int p = 0; p < 8; p++) {
                float a = xf[p], bvv = xm[p];
#pragma unroll
                for (int j = 0; j < 4; j++) {
                    df[j]  += a * fl[p * 4 + j];
                    sf[j]  += a * fl[32 + p * 4 + j];
                    dm[j]  += bvv * fl[p * 4 + j];
                    smv[j] += bvv * fl[32 + p * 4 + j];
                }
            }
            size_t bnext = (size_t)(b0 + bl) * m;
            *(float4*)&xnext[(bnext + s) * 16 + c * 4]    = make_float4(sf[0], sf[1], sf[2], sf[3]);
            *(float4*)&xnext[(bnext + smir) * 16 + c * 4] = make_float4(smv[0], smv[1], smv[2], smv[3]);
            float pd[4], qd[4], px[4], qx[4];
            if (s == 0) {
                float* E = &g_edge[(lev * BB + (b0 + bl)) * 64];
                *(float4*)&E[c * 4]      = make_float4(df[0], df[1], df[2], df[3]);
                *(float4*)&E[16 + c * 4] = make_float4(dm[0], dm[1], dm[2], dm[3]);
                *(float4*)&E[32 + c * 4] = make_float4(sf[0], sf[1], sf[2], sf[3]);
                *(float4*)&E[48 + c * 4] = make_float4(smv[0], smv[1], smv[2], smv[3]);
#pragma unroll
                for (int j = 0; j < 4; j++) { pd[j]=0.f; qd[j]=0.f; px[j]=0.f; qx[j]=0.f; }
            } else {
#pragma unroll
                for (int j = 0; j < 4; j++) {
                    pd[j] = df[j] + dm[j];  qd[j] = df[j] - dm[j];
                    px[j] = sf[j] + smv[j]; qx[j] = sf[j] - smv[j];
                }
            }
            int soff = (bl * 32 + t) * 16 + c * 4;
            *(float4*)&s_dp[soff] = make_float4(pd[0], pd[1], pd[2], pd[3]);
            *(float4*)&s_dq[soff] = make_float4(qd[0], qd[1], qd[2], qd[3]);
            *(float4*)&s_xp[soff] = make_float4(px[0], px[1], px[2], px[3]);
            *(float4*)&s_xq[soff] = make_float4(qx[0], qx[1], qx[2], qx[3]);
        }
        __syncthreads();
        const float* sp = arr ? s_xp : s_dp;
        const float* sq = arr ? s_xq : s_dq;
#pragma unroll 4
        for (int tt = 0; tt < 32; tt++) {
            int base = (bloc * 32 + tt) * 16;
            float4 p0 = *(const float4*)&sp[base + i0];
            float4 p1 = *(const float4*)&sp[base + i0 + 4];
            float4 q0 = *(const float4*)&sq[base + i0];
            float4 q1 = *(const float4*)&sq[base + i0 + 4];
            float4 cv = *(const float4*)&s_tc[tt * 64 + f0];
            float4 sv = *(const float4*)&s_ts[tt * 64 + f0];
            float pp[8] = {p0.x, p0.y, p0.z, p0.w, p1.x, p1.y, p1.z, p1.w};
            float qq[8] = {q0.x, q0.y, q0.z, q0.w, q1.x, q1.y, q1.z, q1.w};
            float cf[4] = {cv.x, cv.y, cv.z, cv.w};
            float sff[4] = {sv.x, sv.y, sv.z, sv.w};
#pragma unroll
            for (int ii = 0; ii < 8; ii++)
#pragma unroll
                for (int ff = 0; ff < 4; ff++) {
                    aR[ii][ff] += pp[ii] * cf[ff];
                    aI[ii][ff] -= qq[ii] * sff[ff];
                }
        }
        __syncthreads();
    }
    float2* P = (float2*)g_part;
    int b = b0 + bloc;
    size_t base = (((size_t)arr * BB + b) * TOTCH + choff + ch) * 64;
#pragma unroll
    for (int ff = 0; ff < 4; ff++)
#pragma unroll
        for (int ii = 0; ii < 8; ii++)
            P[(base + f0 + ff) * 16 + i0 + ii] = make_float2(aR[ii][ff], aI[ii][ff]);
}

// ---------------- merged mix: all 6 levels in one launch ----------------
__global__ void mix_kernel() {
    const int nch[6] = {64, 32, 32, 16, 8, 4};
    const int cho[6] = {0, 64, 96, 128, 144, 152};
    int f = blockIdx.x;
    int b = blockIdx.y;
    int lev = blockIdx.z;
    int m = 16384 >> (lev + 1);
    int tid = threadIdx.x;          // 32 threads
    __shared__ float Dre[16], Dim[16], Xre[16], Xim[16];
    int arr = tid >> 4, i = tid & 15;
    const float2* P = (const float2*)g_part;
    float sre = 0.f, sim = 0.f;
    size_t base = (((size_t)arr * BB + b) * TOTCH + cho[lev]) * 64 + f;
    int nc = nch[lev];
    for (int ch = 0; ch < nc; ch++) {
        float2 p = P[(base + (size_t)ch * 64) * 16 + i];
        sre += p.x; sim += p.y;
    }
    float par = (f & 1) ? -1.f : 1.f;
    const float* E = &g_edge[(lev * BB + b) * 64];
    sre += E[(arr ? 32 : 0) + i] + par * E[(arr ? 48 : 16) + i];
    if (arr == 0) { Dre[i] = sre; Dim[i] = sim; }
    else          { Xre[i] = sre; Xim[i] = sim; }
    __syncthreads();
    float r = 0.f, q = 0.f;
    if (arr == 0) {
#pragma unroll
        for (int ii = 0; ii < 16; ii++) {
            float ar = g_wT[0 * 16384 + f * 256 + ii * 16 + i];
            float ai = g_wT[1 * 16384 + f * 256 + ii * 16 + i];
            r += Dre[ii] * ar - Dim[ii] * ai;
            q += Dre[ii] * ai + Dim[ii] * ar;
            float br = g_wT[2 * 16384 + f * 256 + ii * 16 + i];
            float bi = g_wT[3 * 16384 + f * 256 + ii * 16 + i];
            r += Xre[ii] * br - Xim[ii] * bi;
            q += Xre[ii] * bi + Xim[ii] * br;
        }
    } else {
#pragma unroll
        for (int ii = 0; ii < 16; ii++) {
            float cr = g_wT[4 * 16384 + f * 256 + ii * 16 + i];
            float ci = g_wT[5 * 16384 + f * 256 + ii * 16 + i];
            r += Dre[ii] * cr - Dim[ii] * ci;
            q += Dre[ii] * ci + Dim[ii] * cr;
        }
    }
    float wf = (f == 0) ? (1.0f / (float)m) : (2.0f / (float)m);
    size_t o = (size_t)lev * BB * 4096 + (((size_t)b * 2 + arr) * 128 + 2 * f) * 16 + i;
    g_spec[o]      = r * wf;
    g_spec[o + 16] = -q * wf;
}

// ---------------- Nyquist sample y[m/2] for all 6 shallow levels ----------------
__global__ void nyq_kernel(float* __restrict__ pUd, float* __restrict__ pUs) {
    const int ms[6]   = {8192, 4096, 2048, 1024, 512, 256};
    const int offs[6] = {0, 8192, 12288, 14336, 15360, 15872};
    int lev = blockIdx.x, b = blockIdx.y;
    int tid = threadIdx.x;
    int arr = tid >> 4, j = tid & 15;
    int m = ms[lev];
    const float* sp = g_spec + (size_t)lev * BB * 4096 + ((size_t)b * 2 + arr) * 2048;
    float acc = 0.f;
#pragma unroll
    for (int f = 0; f < 64; f += 2) acc += sp[32 * f + j];
#pragma unroll
    for (int f = 1; f < 64; f += 2) acc -= sp[32 * f + j];
    float* out = (arr ? pUs : pUd) + (size_t)BB * CKD * offs[lev];
    out[((size_t)b * m + m / 2) * 16 + j] = acc;
}

// =================================================================
// inv2: inverse truncated DFT with conjugate symmetry, ALL levels.
// =================================================================
__global__ void __launch_bounds__(128, 3) inv2_kernel(float* __restrict__ pUd,
                                                      float* __restrict__ pUs) {
    const int tstart[6] = {0, 128, 192, 224, 240, 248};
    const int offs[6]   = {0, 8192, 12288, 14336, 15360, 15872};
    extern __shared__ float sm[];
    float* sB = sm;
    float* sA = sB + 16384;
    int tid = threadIdx.x;
    int bx = blockIdx.x;
    int lev;
    if (bx < 128) lev = 0; else if (bx < 192) lev = 1; else if (bx < 224) lev = 2;
    else if (bx < 240) lev = 3; else if (bx < 248) lev = 4; else lev = 5;
    int m = 16384 >> (lev + 1);
    int stride = 1 << lev;
    int t0 = (bx - tstart[lev]) * 32;
    int b0 = blockIdx.y * 4;
    float* outUd = pUd + (size_t)BB * CKD * offs[lev];
    float* outUs = pUs + (size_t)BB * CKD * offs[lev];

    const float4* spec4 = (const float4*)g_spec + (size_t)lev * BB * 1024;
    float4* sB4 = (float4*)sB;
    for (int id = tid; id < 4096; id += 128) {
        int k = id >> 5, col4 = id & 31;
        int bl = col4 >> 3, arr = (col4 >> 2) & 1, j4 = col4 & 3;
        sB4[id] = spec4[(((size_t)(b0 + bl) * 2 + arr) * 128 + k) * 4 + j4];
    }
    const float2* T2 = (const float2*)g_tabT;
    int tl = tid & 31;
    int fq = tid >> 5;
    auto stageA = [&](int st, int buf) {
#pragma unroll
        for (int q = 0; q < 4; q++) {
            int fp = fq * 4 + q;
            int f = st * 16 + fp;
            float2 cs = T2[(size_t)f * 8192 + (size_t)(t0 + tl) * stride];
            sA[buf * 1024 + (2 * fp) * 32 + tl]     = cs.x;
            sA[buf * 1024 + (2 * fp + 1) * 32 + tl] = cs.y;
        }
    };
    stageA(0, 0);
    __syncthreads();

    int cg = tid & 15;
    int tg = tid >> 4;
    float u[4][8] = {}, v[4][8] = {};

    for (int st = 0; st < 4; st++) {
        int cur = st & 1;
        if (st < 3) stageA(st + 1, cur ^ 1);
        const float* A = &sA[cur * 1024];
        const float* Bst = &sB[st * 32 * 128];
#pragma unroll 4
        for (int fp = 0; fp < 16; fp++) {
            float4 ac = *(const float4*)&A[(2 * fp) * 32 + tg * 4];
            float4 as = *(const float4*)&A[(2 * fp + 1) * 32 + tg * 4];
            float4 bu0 = *(const float4*)&Bst[(2 * fp) * 128 + cg * 8];
            float4 bu1 = *(const float4*)&Bst[(2 * fp) * 128 + cg * 8 + 4];
            float4 bv0 = *(const float4*)&Bst[(2 * fp + 1) * 128 + cg * 8];
            float4 bv1 = *(const float4*)&Bst[(2 * fp + 1) * 128 + cg * 8 + 4];
            float acv[4] = {ac.x, ac.y, ac.z, ac.w};
            float asv[4] = {as.x, as.y, as.z, as.w};
            float buv[8] = {bu0.x, bu0.y, bu0.z, bu0.w, bu1.x, bu1.y, bu1.z, bu1.w};
            float bvv[8] = {bv0.x, bv0.y, bv0.z, bv0.w, bv1.x, bv1.y, bv1.z, bv1.w};
#pragma unroll
            for (int r = 0; r < 4; r++)
#pragma unroll
                for (int c = 0; c < 8; c++) {
                    u[r][c] += acv[r] * buv[c];
                    v[r][c] += asv[r] * bvv[c];
                }
        }
        __syncthreads();
    }
    int bl = cg >> 2, arr = (cg >> 1) & 1, j0 = (cg & 1) * 8;
    float* outp = (arr ? outUs : outUd) + ((size_t)(b0 + bl) * m) * 16 + j0;
#pragma unroll
    for (int r = 0; r < 4; r++) {
        int t = t0 + tg * 4 + r;
        float4 y0 = make_float4(u[r][0] + v[r][0], u[r][1] + v[r][1],
                                u[r][2] + v[r][2], u[r][3] + v[r][3]);
        float4 y1 = make_float4(u[r][4] + v[r][4], u[r][5] + v[r][5],
                                u[r][6] + v[r][6], u[r][7] + v[r][7]);
        *(float4*)&outp[(size_t)t * 16]     = y0;
        *(float4*)&outp[(size_t)t * 16 + 4] = y1;
        if (t > 0) {
            size_t tm = (size_t)(m - t);
            float4 z0 = make_float4(u[r][0] - v[r][0], u[r][1] - v[r][1],
                                    u[r][2] - v[r][2], u[r][3] - v[r][3]);
            float4 z1 = make_float4(u[r][4] - v[r][4], u[r][5] - v[r][5],
                                    u[r][6] - v[r][6], u[r][7] - v[r][7]);
            *(float4*)&outp[tm * 16]     = z0;
            *(float4*)&outp[tm * 16 + 4] = z1;
        }
    }
}

// =================================================================
// deep_kernel: levels 6..13 (m=128..1) entirely in smem.
// =================================================================
__global__ void __launch_bounds__(256, 1) deep_kernel(
        const float* __restrict__ xin, float* __restrict__ xout,
        const float* __restrict__ ecd, const float* __restrict__ ecs,
        const float* __restrict__ rce, const float* __restrict__ rco,
        const float* __restrict__ t0w, const float* __restrict__ t0b) {
    extern __shared__ float dsm[];
    float* X0 = dsm;
    float* X1 = X0 + 4096;
    float* D  = X1 + 4096;
    float* UD = D + 2048;
    float* US = UD + 4080;
    float* SP = US + 4080;
    float* MS = SP + 4096;
    __shared__ float fl[148];
    int b = blockIdx.x, tid = threadIdx.x;
    if (tid < 32)       fl[tid] = ecd[tid];
    else if (tid < 64)  fl[tid] = ecs[tid - 32];
    else if (tid < 96)  fl[tid] = rce[tid - 64];
    else if (tid < 128) fl[tid] = rco[tid - 96];
    else if (tid < 144) fl[tid] = t0w[tid - 128];
    else if (tid < 148) fl[tid] = t0b[tid - 144];
    for (int i = tid; i < 4096; i += 256) X0[i] = xin[(size_t)b * 4096 + i];
    __syncthreads();

    float* xc = X0; float* xn = X1;
    int loff[8];
    int off = 0;
    for (int li = 0; li < 8; li++) { loff[li] = off; off += 128 >> li; }

    for (int li = 0; li < 8; li++) {
        int m = 128 >> li;
        int stride = 8192 / m;
        for (int it = tid; it < m * 4; it += 256) {
            int c = it & 3, s = it >> 2;
            float xa[8];
#pragma unroll
            for (int p = 0; p < 4; p++) {
                xa[p]     = xc[(2 * s) * 16 + c * 4 + p];
                xa[p + 4] = xc[(2 * s + 1) * 16 + c * 4 + p];
            }
            float dv[4] = {0, 0, 0, 0}, sv[4] = {0, 0, 0, 0};
#pragma unroll
            for (int p = 0; p < 8; p++) {
                float xv = xa[p];
#pragma unroll
                for (int j = 0; j < 4; j++) {
                    dv[j] += xv * fl[p * 4 + j];
                    sv[j] += xv * fl[32 + p * 4 + j];
                }
            }
#pragma unroll
            for (int j = 0; j < 4; j++) {
                D[s * 16 + c * 4 + j]  = dv[j];
                xn[s * 16 + c * 4 + j] = sv[j];
            }
        }
        __syncthreads();
        int l = (m / 2 + 1 < 64) ? m / 2 + 1 : 64;
        for (int it = tid; it < 2 * l * 16; it += 256) {
            int i = it & 15;
            int f = (it >> 4) % l;
            int arr = it / (16 * l);
            const float* src = arr ? xn : D;
            float re = 0.f, im = 0.f;
            for (int t = 0; t < m; t++) {
                float v = src[t * 16 + i];
                re += v * g_tabc[(t * stride) * 64 + f];
                im -= v * g_tabs[(t * stride) * 64 + f];
            }
            SP[((arr * 64 + f) * 2 + 0) * 16 + i] = re;
            SP[((arr * 64 + f) * 2 + 1) * 16 + i] = im;
        }
        __syncthreads();
        for (int it = tid; it < 2 * l * 16; it += 256) {
            int o = it & 15;
            int f = (it >> 4) % l;
            int arr = it / (16 * l);
            float r = 0.f, q = 0.f;
            if (arr == 0) {
#pragma unroll 4
                for (int i2 = 0; i2 < 16; i2++) {
                    float Dr = SP[((0 * 64 + f) * 2 + 0) * 16 + i2];
                    float Di = SP[((0 * 64 + f) * 2 + 1) * 16 + i2];
                    float Xr = SP[((1 * 64 + f) * 2 + 0) * 16 + i2];
                    float Xi = SP[((1 * 64 + f) * 2 + 1) * 16 + i2];
                    float ar = g_wT[0 * 16384 + f * 256 + i2 * 16 + o];
                    float ai = g_wT[1 * 16384 + f * 256 + i2 * 16 + o];
                    float br = g_wT[2 * 16384 + f * 256 + i2 * 16 + o];
                    float bi = g_wT[3 * 16384 + f * 256 + i2 * 16 + o];
                    r += Dr * ar - Di * ai + Xr * br - Xi * bi;
                    q += Dr * ai + Di * ar + Xr * bi + Xi * br;
                }
            } else {
#pragma unroll 4
                for (int i2 = 0; i2 < 16; i2++) {
                    float Dr = SP[((0 * 64 + f) * 2 + 0) * 16 + i2];
                    float Di = SP[((0 * 64 + f) * 2 + 1) * 16 + i2];
                    float cr = g_wT[4 * 16384 + f * 256 + i2 * 16 + o];
                    float ci = g_wT[5 * 16384 + f * 256 + i2 * 16 + o];
                    r += Dr * cr - Di * ci;
                    q += Dr * ci + Di * cr;
                }
            }
            float wf = (f == 0 || 2 * f == m) ? (1.0f / (float)m) : (2.0f / (float)m);
            MS[((arr * 64 + f) * 2 + 0) * 16 + o] = r * wf;
            MS[((arr * 64 + f) * 2 + 1) * 16 + o] = q * wf;
        }
        __syncthreads();
        for (int it = tid; it < 2 * m * 16; it += 256) {
            int o = it & 15;
            int t = (it >> 4) % m;
            int arr = it / (16 * m);
            float acc = 0.f;
            for (int f = 0; f < l; f++) {
                float r = MS[((arr * 64 + f) * 2 + 0) * 16 + o];
                float q = MS[((arr * 64 + f) * 2 + 1) * 16 + o];
                acc += r * g_tabc[(t * stride) * 64 + f] - q * g_tabs[(t * stride) * 64 + f];
            }
            (arr ? US : UD)[(loff[li] + t) * 16 + o] = acc;
        }
        __syncthreads();
        float* tmp = xc; xc = xn; xn = tmp;
    }
    if (tid < 16) {
        int c = tid >> 2, o = tid & 3;
        float acc = fl[144 + o];
#pragma unroll
        for (int p = 0; p < 4; p++) acc += xc[c * 4 + p] * fl[128 + o * 4 + p];
        xn[tid] = acc;
    }
    __syncthreads();
    { float* tmp = xc; xc = xn; xn = tmp; }
    for (int li = 7; li >= 0; li--) {
        int m = 128 >> li;
        for (int it = tid; it < m * 4; it += 256) {
            int c = it & 3, s = it >> 2;
            float xs[4], ud[4];
#pragma unroll
            for (int j = 0; j < 4; j++) {
                xs[j] = xc[s * 16 + c * 4 + j] + US[(loff[li] + s) * 16 + c * 4 + j];
                ud[j] = UD[(loff[li] + s) * 16 + c * 4 + j];
            }
            float e[4] = {0, 0, 0, 0}, o4[4] = {0, 0, 0, 0};
#pragma unroll
            for (int p = 0; p < 4; p++)
#pragma unroll
                for (int j = 0; j < 4; j++) {
                    e[j]  += xs[p] * fl[64 + p * 4 + j] + ud[p] * fl[64 + (p + 4) * 4 + j];
                    o4[j] += xs[p] * fl[96 + p * 4 + j] + ud[p] * fl[96 + (p + 4) * 4 + j];
                }
#pragma unroll
            for (int j = 0; j < 4; j++) {
                xn[(2 * s) * 16 + c * 4 + j]     = e[j];
                xn[(2 * s + 1) * 16 + c * 4 + j] = o4[j];
            }
        }
        __syncthreads();
        float* tmp = xc; xc = xn; xn = tmp;
    }
    for (int i = tid; i < 4096; i += 256) xout[(size_t)b * 4096 + i] = xc[i];
}

// ---------------- reconstruction step (levels 0-5) ----------------
__global__ void recon_kernel(const float* __restrict__ xin, const float* __restrict__ Ud,
                             const float* __restrict__ Us, const float* __restrict__ rce,
                             const float* __restrict__ rco, float* __restrict__ out, int m) {
    __shared__ float se[32], so[32];
    int tid = threadIdx.x;
    if (tid < 32)      se[tid]      = rce[tid];
    else if (tid < 64) so[tid - 32] = rco[tid - 32];
    __syncthreads();
    int idx = blockIdx.x * blockDim.x + tid;
    if (idx >= BB * m * 4) return;
    int c = idx & 3;
    int s = (idx >> 2) % m;
    int b = idx / (m * 4);
    size_t r = ((size_t)b * m + s) * 16 + c * 4;
    float4 xv = *(const float4*)&xin[r];
    float4 uv = *(const float4*)&Us[r];
    float4 dv = *(const float4*)&Ud[r];
    float xs[4] = {xv.x + uv.x, xv.y + uv.y, xv.z + uv.z, xv.w + uv.w};
    float ud[4] = {dv.x, dv.y, dv.z, dv.w};
    float e[4] = {0, 0, 0, 0}, o[4] = {0, 0, 0, 0};
#pragma unroll
    for (int p = 0; p < 4; p++)
#pragma unroll
        for (int j = 0; j < 4; j++) {
            e[j] += xs[p] * se[p * 4 + j] + ud[p] * se[(p + 4) * 4 + j];
            o[j] += xs[p] * so[p * 4 + j] + ud[p] * so[(p + 4) * 4 + j];
        }
    size_t w = ((size_t)b * 2 * m + 2 * s) * 16 + c * 4;
    *(float4*)&out[w]      = make_float4(e[0], e[1], e[2], e[3]);
    *(float4*)&out[w + 16] = make_float4(o[0], o[1], o[2], o[3]);
}

// ---------------- side streams + events (host objects, created once) ----------------
struct SideStreams {
    cudaStream_t sB = nullptr, sC = nullptr;
    cudaEvent_t evRoot = nullptr, evB = nullptr, evD = nullptr,
                evC = nullptr, evMix = nullptr, evNyq = nullptr;
    void ensure() {
        if (sB) return;
        cudaStreamCreateWithFlags(&sB, cudaStreamNonBlocking);
        cudaStreamCreateWithFlags(&sC, cudaStreamNonBlocking);
        cudaEventCreateWithFlags(&evRoot, cudaEventDisableTiming);
        cudaEventCreateWithFlags(&evB,    cudaEventDisableTiming);
        cudaEventCreateWithFlags(&evD,    cudaEventDisableTiming);
        cudaEventCreateWithFlags(&evC,    cudaEventDisableTiming);
        cudaEventCreateWithFlags(&evMix,  cudaEventDisableTiming);
        cudaEventCreateWithFlags(&evNyq,  cudaEventDisableTiming);
    }
};
static SideStreams g_ss;

// ---------------- host orchestration ----------------
extern "C" void kernel_launch(void* const* d_in, const int* in_sizes, int n_in,
                              void* d_out, int out_size) {
    const float* x_in = (const float*)d_in[0];
    const float* ec_s = (const float*)d_in[1];
    const float* ec_d = (const float*)d_in[2];
    const float* rc_e = (const float*)d_in[3];
    const float* rc_o = (const float*)d_in[4];
    const float* t0_w = (const float*)d_in[5];
    const float* t0_b = (const float*)d_in[6];

    g_ss.ensure();

    const int DFWD_SM = 12288 * 4;
    const int INV_SM  = (16384 + 2048) * 4;
    const int DEEP_SM = (4096 + 4096 + 2048 + 4080 + 4080 + 4096 + 4096) * 4;
    cudaFuncSetAttribute(dfwd_kernel, cudaFuncAttributeMaxDynamicSharedMemorySize, DFWD_SM);
    cudaFuncSetAttribute(inv2_kernel, cudaFuncAttributeMaxDynamicSharedMemorySize, INV_SM);
    cudaFuncSetAttribute(deep_kernel, cudaFuncAttributeMaxDynamicSharedMemorySize, DEEP_SM);

    float *px0, *px1, *pd, *pUd, *pUs;
    cudaGetSymbolAddress((void**)&px0, g_x0);
    cudaGetSymbolAddress((void**)&px1, g_x1);
    cudaGetSymbolAddress((void**)&pd,  g_d);
    cudaGetSymbolAddress((void**)&pUd, g_Ud);
    cudaGetSymbolAddress((void**)&pUs, g_Us);

    // ---- fork stream B at root: tab_T + wprep (independent of dfwd chain) ----
    cudaEventRecord(g_ss.evRoot, 0);
    cudaStreamWaitEvent(g_ss.sB, g_ss.evRoot, 0);
    tab_T_kernel<<<2048, 256, 0, g_ss.sB>>>();
    wprep_kernel<<<(6 * 16384 + 255) / 256, 256, 0, g_ss.sB>>>(
        (const float*)d_in[7], (const float*)d_in[8], (const float*)d_in[9],
        (const float*)d_in[10], (const float*)d_in[11], (const float*)d_in[12]);
    cudaEventRecord(g_ss.evB, g_ss.sB);

    // ---- main stream: tab_row, then dfwd chain ----
    tab_row_kernel<<<2048, 256>>>();

    float* xb[2] = {px0, px1};
    const int nchunks[6] = {64, 32, 32, 16, 8, 4};
    const int choffs[6]  = {0, 64, 96, 128, 144, 152};
    size_t offs[6];
    size_t off = 0;
    const float* src = x_in;

    for (int lev = 0; lev < 6; lev++) {
        int m = NN >> (lev + 1);                 // 8192..256
        offs[lev] = off;
        int stride = MAXM / m;
        float* xnext = xb[lev & 1];
        dfwd_kernel<<<dim3(8, nchunks[lev]), 256, DFWD_SM>>>(
            src, xnext, ec_d, ec_s, m, stride, nchunks[lev], choffs[lev], lev);
        off += m;
        src = xnext;
    }

    // ---- fork stream C: deep_kernel (needs dfwd5 + wprep), concurrent with mix/inv2 ----
    cudaEventRecord(g_ss.evD, 0);
    cudaStreamWaitEvent(g_ss.sC, g_ss.evD, 0);
    cudaStreamWaitEvent(g_ss.sC, g_ss.evB, 0);
    deep_kernel<<<BB, 256, DEEP_SM, g_ss.sC>>>(src, pd, ec_d, ec_s, rc_e, rc_o, t0_w, t0_b);
    cudaEventRecord(g_ss.evC, g_ss.sC);

    // ---- main: mix (needs wprep), nyq forked to B, inv2 (needs tab_T) ----
    cudaStreamWaitEvent(0, g_ss.evB, 0);
    mix_kernel<<<dim3(64, BB, 6), 32>>>();
    cudaEventRecord(g_ss.evMix, 0);
    cudaStreamWaitEvent(g_ss.sB, g_ss.evMix, 0);
    nyq_kernel<<<dim3(6, BB), 32, 0, g_ss.sB>>>(pUd, pUs);
    cudaEventRecord(g_ss.evNyq, g_ss.sB);
    inv2_kernel<<<dim3(252, 8), 128, INV_SM>>>(pUd, pUs);

    // ---- join deep + nyq, then reconstruction levels 5..0 ----
    cudaStreamWaitEvent(0, g_ss.evC, 0);
    cudaStreamWaitEvent(0, g_ss.evNyq, 0);
    const float* curx = pd;
    int flip = 0;
    for (int lev = 5; lev >= 0; lev--) {
        int m = NN >> (lev + 1);
        float* dst = (lev == 0) ? (float*)d_out : xb[flip];
        int total = BB * m * 4;
        recon_kernel<<<(total + 255) / 256, 256>>>(
            curx, pUd + (size_t)BB * CKD * offs[lev], pUs + (size_t)BB * CKD * offs[lev],
            rc_e, rc_o, dst, m);
        curx = dst;
        flip ^= 1;
    }
}